// round 1
// baseline (speedup 1.0000x reference)
#include <cuda_runtime.h>
#include <cuda_bf16.h>

#define N_NODES 50000
#define E_EDGES 800000
#define DD 128
#define GG 256
#define CC 16
#define NLAYERS 4   // L-1 GIN layers
#define BN_EPS 1e-5f
#define APPLY_ROWS 64

// ---------------- device scratch (no allocation allowed) ----------------
__device__ float g_bufA[(size_t)N_NODES * DD];   // h
__device__ float g_bufB[(size_t)N_NODES * DD];   // pooled / z2
__device__ float g_bufC[(size_t)N_NODES * DD];   // z1
__device__ float g_gp[5 * GG * DD];              // per-layer graph pools
__device__ float g_stats[NLAYERS * 2 * 2 * DD];  // sums / sumsq per (layer,bn)
__device__ float g_ss[NLAYERS * 2 * 2 * DD];     // scale / shift per (layer,bn)
__device__ int   g_counts[N_NODES];
__device__ int   g_rowptr[N_NODES + 1];
__device__ int   g_cursor[N_NODES];
__device__ int   g_srcsorted[E_EDGES];

// ---------------- utility: zero scratch ----------------
__global__ void zero_kernel(float* a, int na, float* b, int nb, int* c, int nc) {
    int i = blockIdx.x * blockDim.x + threadIdx.x;
    int stride = gridDim.x * blockDim.x;
    for (int j = i; j < na; j += stride) a[j] = 0.f;
    for (int j = i; j < nb; j += stride) b[j] = 0.f;
    for (int j = i; j < nc; j += stride) c[j] = 0;
}

// ---------------- CSR build ----------------
__global__ void count_kernel(const int* __restrict__ edst, int* counts) {
    int e = blockIdx.x * blockDim.x + threadIdx.x;
    if (e < E_EDGES) atomicAdd(&counts[edst[e]], 1);
}

__global__ void scan_kernel(const int* __restrict__ counts, int* rowptr, int* cursor) {
    __shared__ int warp_sums[32];
    __shared__ int carry_s;
    int tid = threadIdx.x;
    int lane = tid & 31, warp = tid >> 5;
    if (tid == 0) carry_s = 0;
    __syncthreads();
    for (int base = 0; base < N_NODES; base += 1024) {
        int i = base + tid;
        int v = (i < N_NODES) ? counts[i] : 0;
        int x = v;
        #pragma unroll
        for (int off = 1; off < 32; off <<= 1) {
            int y = __shfl_up_sync(0xffffffffu, x, off);
            if (lane >= off) x += y;
        }
        if (lane == 31) warp_sums[warp] = x;
        __syncthreads();
        if (warp == 0) {
            int s = warp_sums[lane];
            #pragma unroll
            for (int off = 1; off < 32; off <<= 1) {
                int y = __shfl_up_sync(0xffffffffu, s, off);
                if (lane >= off) s += y;
            }
            warp_sums[lane] = s;
        }
        __syncthreads();
        int excl = carry_s + (warp ? warp_sums[warp - 1] : 0) + x - v;
        if (i < N_NODES) { rowptr[i] = excl; cursor[i] = excl; }
        __syncthreads();
        if (tid == 1023) carry_s = excl + v;
        __syncthreads();
    }
    if (tid == 0) rowptr[N_NODES] = carry_s;
}

__global__ void fill_kernel(const int* __restrict__ esrc, const int* __restrict__ edst,
                            int* cursor, int* srcsorted) {
    int e = blockIdx.x * blockDim.x + threadIdx.x;
    if (e < E_EDGES) {
        int pos = atomicAdd(&cursor[edst[e]], 1);
        srcsorted[pos] = esrc[e];
    }
}

// ---------------- SpMM: pooled = (1+eps)*h + sum_{src in row(dst)} h[src] ----------------
__global__ void spmm_kernel(const float* __restrict__ h, const int* __restrict__ rowptr,
                            const int* __restrict__ srcs, const float* __restrict__ eps,
                            int l, float* __restrict__ out) {
    int node = blockIdx.x;
    int tid = threadIdx.x;  // 128
    float scale = 1.0f + __ldg(eps + l);
    float acc = scale * __ldg(h + (size_t)node * DD + tid);
    int s = __ldg(rowptr + node), e = __ldg(rowptr + node + 1);
    int i = s;
    // unroll by 4 for MLP
    for (; i + 3 < e; i += 4) {
        int s0 = __ldg(srcs + i + 0);
        int s1 = __ldg(srcs + i + 1);
        int s2 = __ldg(srcs + i + 2);
        int s3 = __ldg(srcs + i + 3);
        float v0 = __ldg(h + (size_t)s0 * DD + tid);
        float v1 = __ldg(h + (size_t)s1 * DD + tid);
        float v2 = __ldg(h + (size_t)s2 * DD + tid);
        float v3 = __ldg(h + (size_t)s3 * DD + tid);
        acc += v0 + v1 + v2 + v3;
    }
    for (; i < e; i++) {
        int s0 = __ldg(srcs + i);
        acc += __ldg(h + (size_t)s0 * DD + tid);
    }
    out[(size_t)node * DD + tid] = acc;
}

// ---------------- GEMM: C[M,128] = op(A)[M,128] @ W[128,128] + bias ----------------
// op(A) = A if ss==nullptr, else relu(scale*A + shift) columnwise (fused BN1+ReLU input).
#define BM 128
#define BK 16
__global__ __launch_bounds__(256) void gemm_kernel(
    const float* __restrict__ A, const float* __restrict__ W,
    const float* __restrict__ bias, const float* __restrict__ ss,
    float* __restrict__ C, int M) {
    __shared__ float As[BK][BM];
    __shared__ float Ws[BK][DD];
    int tid = threadIdx.x;
    int row0 = blockIdx.x * BM;
    int tm = (tid / 16) * 8;
    int tn = (tid % 16) * 8;
    float acc[8][8];
    #pragma unroll
    for (int i = 0; i < 8; i++)
        #pragma unroll
        for (int j = 0; j < 8; j++) acc[i][j] = 0.f;

    for (int kt = 0; kt < DD; kt += BK) {
        // load A tile 128x16 (each thread: 2 float4)
        #pragma unroll
        for (int it = 0; it < 2; it++) {
            int idx = tid + it * 256;        // 0..511 float4 slots
            int m = idx >> 2;                // 0..127
            int ks = (idx & 3) * 4;          // 0,4,8,12
            int grow = row0 + m;
            float4 v = make_float4(0.f, 0.f, 0.f, 0.f);
            if (grow < M) v = *reinterpret_cast<const float4*>(A + (size_t)grow * DD + kt + ks);
            if (ss) {
                float4 sc = *reinterpret_cast<const float4*>(ss + kt + ks);
                float4 sh = *reinterpret_cast<const float4*>(ss + DD + kt + ks);
                v.x = fmaxf(0.f, fmaf(sc.x, v.x, sh.x));
                v.y = fmaxf(0.f, fmaf(sc.y, v.y, sh.y));
                v.z = fmaxf(0.f, fmaf(sc.z, v.z, sh.z));
                v.w = fmaxf(0.f, fmaf(sc.w, v.w, sh.w));
            }
            As[ks + 0][m] = v.x;
            As[ks + 1][m] = v.y;
            As[ks + 2][m] = v.z;
            As[ks + 3][m] = v.w;
        }
        // load W tile 16x128
        #pragma unroll
        for (int it = 0; it < 2; it++) {
            int idx = tid + it * 256;
            int k = idx >> 5;                // 0..15
            int n4 = (idx & 31) * 4;
            float4 v = *reinterpret_cast<const float4*>(W + (size_t)(kt + k) * DD + n4);
            *reinterpret_cast<float4*>(&Ws[k][n4]) = v;
        }
        __syncthreads();
        #pragma unroll
        for (int k = 0; k < BK; k++) {
            float a[8], b[8];
            #pragma unroll
            for (int i = 0; i < 8; i++) a[i] = As[k][tm + i];
            #pragma unroll
            for (int j = 0; j < 8; j++) b[j] = Ws[k][tn + j];
            #pragma unroll
            for (int i = 0; i < 8; i++)
                #pragma unroll
                for (int j = 0; j < 8; j++) acc[i][j] = fmaf(a[i], b[j], acc[i][j]);
        }
        __syncthreads();
    }
    // epilogue: + bias, store
    #pragma unroll
    for (int i = 0; i < 8; i++) {
        int grow = row0 + tm + i;
        if (grow < M) {
            #pragma unroll
            for (int j = 0; j < 8; j += 4) {
                float4 o;
                o.x = acc[i][j + 0] + __ldg(bias + tn + j + 0);
                o.y = acc[i][j + 1] + __ldg(bias + tn + j + 1);
                o.z = acc[i][j + 2] + __ldg(bias + tn + j + 2);
                o.w = acc[i][j + 3] + __ldg(bias + tn + j + 3);
                *reinterpret_cast<float4*>(C + (size_t)grow * DD + tn + j) = o;
            }
        }
    }
}

// ---------------- column stats (sum, sumsq) ----------------
__global__ void colstats_kernel(const float* __restrict__ z, float* __restrict__ stats) {
    __shared__ float s1[256], s2[256];
    int tid = threadIdx.x;
    int col = tid & (DD - 1);
    int half = tid >> 7;
    float sum = 0.f, sq = 0.f;
    for (int r = blockIdx.x * 2 + half; r < N_NODES; r += gridDim.x * 2) {
        float v = z[(size_t)r * DD + col];
        sum += v;
        sq = fmaf(v, v, sq);
    }
    s1[tid] = sum; s2[tid] = sq;
    __syncthreads();
    if (tid < DD) {
        atomicAdd(stats + col, s1[tid] + s1[tid + DD]);
        atomicAdd(stats + DD + col, s2[tid] + s2[tid + DD]);
    }
}

__global__ void bn_finalize(const float* __restrict__ stats, const float* __restrict__ g,
                            const float* __restrict__ beta, float* __restrict__ ss) {
    int c = threadIdx.x;
    const float invN = 1.0f / (float)N_NODES;
    float mean = stats[c] * invN;
    float var = stats[DD + c] * invN - mean * mean;
    float rstd = rsqrtf(var + BN_EPS);
    float scale = __ldg(g + c) * rstd;
    ss[c] = scale;
    ss[DD + c] = __ldg(beta + c) - scale * mean;
}

// ---------------- BN2+ReLU apply + per-graph pooling (graph_ids sorted) ----------------
__global__ void apply_pool_kernel(const float* __restrict__ z, const float* __restrict__ ss,
                                  const int* __restrict__ gid, float* __restrict__ h,
                                  float* __restrict__ gp) {
    int tid = threadIdx.x;  // 128
    int r0 = blockIdx.x * APPLY_ROWS;
    if (r0 >= N_NODES) return;
    int rend = min(r0 + APPLY_ROWS, N_NODES);
    float sc = __ldg(ss + tid), sh = __ldg(ss + DD + tid);
    float acc = 0.f;
    int curg = __ldg(gid + r0);
    for (int r = r0; r < rend; r++) {
        float v = z[(size_t)r * DD + tid];
        float hv = fmaxf(0.f, fmaf(sc, v, sh));
        h[(size_t)r * DD + tid] = hv;
        int g = __ldg(gid + r);
        if (g != curg) {
            atomicAdd(gp + (size_t)curg * DD + tid, acc);
            acc = 0.f;
            curg = g;
        }
        acc += hv;
    }
    atomicAdd(gp + (size_t)curg * DD + tid, acc);
}

// pooling of raw x (layer 0 hidden representation)
__global__ void pool_x_kernel(const float* __restrict__ x, const int* __restrict__ gid,
                              float* __restrict__ gp) {
    int tid = threadIdx.x;
    int r0 = blockIdx.x * APPLY_ROWS;
    if (r0 >= N_NODES) return;
    int rend = min(r0 + APPLY_ROWS, N_NODES);
    float acc = 0.f;
    int curg = __ldg(gid + r0);
    for (int r = r0; r < rend; r++) {
        float v = x[(size_t)r * DD + tid];
        int g = __ldg(gid + r);
        if (g != curg) {
            atomicAdd(gp + (size_t)curg * DD + tid, acc);
            acc = 0.f;
            curg = g;
        }
        acc += v;
    }
    atomicAdd(gp + (size_t)curg * DD + tid, acc);
}

// ---------------- readout: out[g,c] = sum_l gp[l][g] @ Wp[l] + sum_l bp[l] ----------------
__global__ void readout_kernel(const float* __restrict__ gp, const float* __restrict__ Wp,
                               const float* __restrict__ bp, float* __restrict__ out) {
    int g = blockIdx.x;
    int tid = threadIdx.x;  // 128
    int lane = tid & 31, warp = tid >> 5;
    float partial[CC];
    #pragma unroll
    for (int c = 0; c < CC; c++) partial[c] = 0.f;
    for (int l = 0; l < 5; l++) {
        float v = gp[((size_t)l * GG + g) * DD + tid];
        const float* w = Wp + ((size_t)l * DD + tid) * CC;
        #pragma unroll
        for (int c = 0; c < CC; c++) partial[c] = fmaf(v, __ldg(w + c), partial[c]);
    }
    __shared__ float red[4][CC];
    #pragma unroll
    for (int c = 0; c < CC; c++) {
        float v = partial[c];
        #pragma unroll
        for (int off = 16; off; off >>= 1) v += __shfl_down_sync(0xffffffffu, v, off);
        if (lane == 0) red[warp][c] = v;
    }
    __syncthreads();
    if (tid < CC) {
        float s = red[0][tid] + red[1][tid] + red[2][tid] + red[3][tid];
        float b = 0.f;
        #pragma unroll
        for (int l = 0; l < 5; l++) b += __ldg(bp + l * CC + tid);
        out[g * CC + tid] = s + b;
    }
}

// ---------------- host orchestration ----------------
extern "C" void kernel_launch(void* const* d_in, const int* in_sizes, int n_in,
                              void* d_out, int out_size) {
    const float* x     = (const float*)d_in[0];
    const float* eps   = (const float*)d_in[1];
    const float* W1    = (const float*)d_in[2];
    const float* b1    = (const float*)d_in[3];
    const float* g1    = (const float*)d_in[4];
    const float* beta1 = (const float*)d_in[5];
    const float* W2    = (const float*)d_in[6];
    const float* b2    = (const float*)d_in[7];
    const float* g2    = (const float*)d_in[8];
    const float* beta2 = (const float*)d_in[9];
    const float* Wp    = (const float*)d_in[10];
    const float* bp    = (const float*)d_in[11];
    const int* esrc    = (const int*)d_in[12];
    const int* edst    = (const int*)d_in[13];
    const int* gid     = (const int*)d_in[14];
    float* out = (float*)d_out;

    float *bufA, *bufB, *bufC, *gp, *stats, *ssbuf;
    int *counts, *rowptr, *cursor, *srcsorted;
    cudaGetSymbolAddress((void**)&bufA, g_bufA);
    cudaGetSymbolAddress((void**)&bufB, g_bufB);
    cudaGetSymbolAddress((void**)&bufC, g_bufC);
    cudaGetSymbolAddress((void**)&gp, g_gp);
    cudaGetSymbolAddress((void**)&stats, g_stats);
    cudaGetSymbolAddress((void**)&ssbuf, g_ss);
    cudaGetSymbolAddress((void**)&counts, g_counts);
    cudaGetSymbolAddress((void**)&rowptr, g_rowptr);
    cudaGetSymbolAddress((void**)&cursor, g_cursor);
    cudaGetSymbolAddress((void**)&srcsorted, g_srcsorted);

    zero_kernel<<<256, 256>>>(gp, 5 * GG * DD, stats, NLAYERS * 2 * 2 * DD, counts, N_NODES);
    count_kernel<<<(E_EDGES + 255) / 256, 256>>>(edst, counts);
    scan_kernel<<<1, 1024>>>(counts, rowptr, cursor);
    fill_kernel<<<(E_EDGES + 255) / 256, 256>>>(esrc, edst, cursor, srcsorted);
    pool_x_kernel<<<(N_NODES + APPLY_ROWS - 1) / APPLY_ROWS, 128>>>(x, gid, gp);

    const int gemm_grid = (N_NODES + BM - 1) / BM;
    const float* h = x;
    for (int l = 0; l < NLAYERS; l++) {
        float* st1 = stats + (l * 2 + 0) * 2 * DD;
        float* st2 = stats + (l * 2 + 1) * 2 * DD;
        float* ss1 = ssbuf + (l * 2 + 0) * 2 * DD;
        float* ss2 = ssbuf + (l * 2 + 1) * 2 * DD;

        spmm_kernel<<<N_NODES, 128>>>(h, rowptr, srcsorted, eps, l, bufB);
        gemm_kernel<<<gemm_grid, 256>>>(bufB, W1 + (size_t)l * DD * DD, b1 + l * DD,
                                        nullptr, bufC, N_NODES);
        colstats_kernel<<<256, 256>>>(bufC, st1);
        bn_finalize<<<1, DD>>>(st1, g1 + l * DD, beta1 + l * DD, ss1);
        gemm_kernel<<<gemm_grid, 256>>>(bufC, W2 + (size_t)l * DD * DD, b2 + l * DD,
                                        ss1, bufB, N_NODES);
        colstats_kernel<<<256, 256>>>(bufB, st2);
        bn_finalize<<<1, DD>>>(st2, g2 + l * DD, beta2 + l * DD, ss2);
        apply_pool_kernel<<<(N_NODES + APPLY_ROWS - 1) / APPLY_ROWS, 128>>>(
            bufB, ss2, gid, bufA, gp + (size_t)(l + 1) * GG * DD);
        h = bufA;
    }
    readout_kernel<<<GG, 128>>>(gp, Wp, bp, out);
}

// round 3
// speedup vs baseline: 1.5130x; 1.5130x over previous
#include <cuda_runtime.h>
#include <cuda_bf16.h>
#include <cstdint>

#define N_NODES 50000
#define E_EDGES 800000
#define DD 128
#define GG 256
#define CC 16
#define NLAYERS 4   // L-1 GIN layers
#define BN_EPS 1e-5f
#define APPLY_ROWS 64
#define MTILES ((N_NODES + 127) / 128)   // 391

// ---------------- device scratch (no allocation allowed) ----------------
__device__ float g_h [(size_t)N_NODES * DD];    // hidden (fp32)
__device__ float g_z1[(size_t)N_NODES * DD];    // z1 (pre-BN1)
__device__ float g_z2[(size_t)N_NODES * DD];    // z2 (pre-BN2)
__device__ __nv_bfloat16 g_ahi[(size_t)N_NODES * DD];  // GEMM A operand hi
__device__ __nv_bfloat16 g_alo[(size_t)N_NODES * DD];  // GEMM A operand lo
__device__ __nv_bfloat16 g_whi[8 * DD * DD];    // transposed split weights [n][k]
__device__ __nv_bfloat16 g_wlo[8 * DD * DD];
__device__ float g_gp[5 * GG * DD];             // per-layer graph pools
__device__ float g_stats[NLAYERS * 2 * 2 * DD]; // sums / sumsq per (layer,bn)
__device__ float g_ss[NLAYERS * 2 * 2 * DD];    // scale / shift per (layer,bn)
__device__ int   g_counts[N_NODES];
__device__ int   g_rowptr[N_NODES + 1];
__device__ int   g_cursor[N_NODES];
__device__ int   g_srcsorted[E_EDGES];

// ================= warp-MMA helpers (portable, sm_80+) =================
__device__ __forceinline__ uint32_t smem_u32(const void* p) {
    uint32_t a;
    asm("{ .reg .u64 t; cvta.to.shared.u64 t, %1; cvt.u32.u64 %0, t; }" : "=r"(a) : "l"(p));
    return a;
}
__device__ __forceinline__ void ldm4(uint32_t* r, uint32_t addr) {
    asm volatile("ldmatrix.sync.aligned.m8n8.x4.shared.b16 {%0,%1,%2,%3}, [%4];"
        : "=r"(r[0]), "=r"(r[1]), "=r"(r[2]), "=r"(r[3]) : "r"(addr));
}
__device__ __forceinline__ void mma16816(float* d, const uint32_t* a, const uint32_t* b) {
    asm volatile("mma.sync.aligned.m16n8k16.row.col.f32.bf16.bf16.f32 "
        "{%0,%1,%2,%3}, {%4,%5,%6,%7}, {%8,%9}, {%0,%1,%2,%3};"
        : "+f"(d[0]), "+f"(d[1]), "+f"(d[2]), "+f"(d[3])
        : "r"(a[0]), "r"(a[1]), "r"(a[2]), "r"(a[3]), "r"(b[0]), "r"(b[1]));
}
// swizzled byte offset within a [128 rows x 64 bf16] tile (row = 128 B = 8 x 16B chunks)
__device__ __forceinline__ uint32_t sw(int row, int c8) {
    return (uint32_t)(row * 128 + ((c8 ^ (row & 7)) * 16));
}

// ---------------- utility: zero scratch ----------------
__global__ void zero_kernel(float* a, int na, float* b, int nb, int* c, int nc) {
    int i = blockIdx.x * blockDim.x + threadIdx.x;
    int stride = gridDim.x * blockDim.x;
    for (int j = i; j < na; j += stride) a[j] = 0.f;
    for (int j = i; j < nb; j += stride) b[j] = 0.f;
    for (int j = i; j < nc; j += stride) c[j] = 0;
}

// ---------------- CSR build ----------------
__global__ void count_kernel(const int* __restrict__ edst, int* counts) {
    int e = blockIdx.x * blockDim.x + threadIdx.x;
    if (e < E_EDGES) atomicAdd(&counts[edst[e]], 1);
}

__global__ void scan_kernel(const int* __restrict__ counts, int* rowptr, int* cursor) {
    __shared__ int warp_sums[32];
    __shared__ int carry_s;
    int tid = threadIdx.x;
    int lane = tid & 31, warp = tid >> 5;
    if (tid == 0) carry_s = 0;
    __syncthreads();
    for (int base = 0; base < N_NODES; base += 1024) {
        int i = base + tid;
        int v = (i < N_NODES) ? counts[i] : 0;
        int x = v;
        #pragma unroll
        for (int off = 1; off < 32; off <<= 1) {
            int y = __shfl_up_sync(0xffffffffu, x, off);
            if (lane >= off) x += y;
        }
        if (lane == 31) warp_sums[warp] = x;
        __syncthreads();
        if (warp == 0) {
            int s = warp_sums[lane];
            #pragma unroll
            for (int off = 1; off < 32; off <<= 1) {
                int y = __shfl_up_sync(0xffffffffu, s, off);
                if (lane >= off) s += y;
            }
            warp_sums[lane] = s;
        }
        __syncthreads();
        int excl = carry_s + (warp ? warp_sums[warp - 1] : 0) + x - v;
        if (i < N_NODES) { rowptr[i] = excl; cursor[i] = excl; }
        __syncthreads();
        if (tid == 1023) carry_s = excl + v;
        __syncthreads();
    }
    if (tid == 0) rowptr[N_NODES] = carry_s;
}

__global__ void fill_kernel(const int* __restrict__ esrc, const int* __restrict__ edst,
                            int* cursor, int* srcsorted) {
    int e = blockIdx.x * blockDim.x + threadIdx.x;
    if (e < E_EDGES) {
        int pos = atomicAdd(&cursor[edst[e]], 1);
        srcsorted[pos] = esrc[e];
    }
}

// ---------------- weight prep: transpose + bf16 hi/lo split ----------------
// out[m][n][k] = W_m[k][n]; m = 0..3 -> W1 layers, 4..7 -> W2 layers
__global__ void wprep_kernel(const float* __restrict__ W1, const float* __restrict__ W2,
                             __nv_bfloat16* __restrict__ whi, __nv_bfloat16* __restrict__ wlo) {
    int m = blockIdx.x;
    int kb = blockIdx.y;
    int n = threadIdx.x;
    const float* W = (m < 4) ? (W1 + (size_t)m * DD * DD) : (W2 + (size_t)(m - 4) * DD * DD);
    for (int k = kb * 16; k < kb * 16 + 16; k++) {
        float w = W[(size_t)k * DD + n];
        __nv_bfloat16 h16 = __float2bfloat16(w);
        float hif = __bfloat162float(h16);
        size_t o = ((size_t)m * DD + n) * DD + k;
        whi[o] = h16;
        wlo[o] = __float2bfloat16(w - hif);
    }
}

// ---------------- SpMM + eps + bf16 split ----------------
__global__ void spmm_split_kernel(const float* __restrict__ h, const int* __restrict__ rowptr,
                                  const int* __restrict__ srcs, const float* __restrict__ eps,
                                  int l, __nv_bfloat16* __restrict__ ohi,
                                  __nv_bfloat16* __restrict__ olo) {
    int node = blockIdx.x;
    int tid = threadIdx.x;  // 128
    float scale = 1.0f + __ldg(eps + l);
    float acc = scale * __ldg(h + (size_t)node * DD + tid);
    int s = __ldg(rowptr + node), e = __ldg(rowptr + node + 1);
    int i = s;
    for (; i + 3 < e; i += 4) {
        int s0 = __ldg(srcs + i + 0);
        int s1 = __ldg(srcs + i + 1);
        int s2 = __ldg(srcs + i + 2);
        int s3 = __ldg(srcs + i + 3);
        acc += __ldg(h + (size_t)s0 * DD + tid) + __ldg(h + (size_t)s1 * DD + tid)
             + __ldg(h + (size_t)s2 * DD + tid) + __ldg(h + (size_t)s3 * DD + tid);
    }
    for (; i < e; i++) acc += __ldg(h + (size_t)__ldg(srcs + i) * DD + tid);
    __nv_bfloat16 h16 = __float2bfloat16(acc);
    float hif = __bfloat162float(h16);
    size_t o = (size_t)node * DD + tid;
    ohi[o] = h16;
    olo[o] = __float2bfloat16(acc - hif);
}

// ---------------- HMMA GEMM: C[M,128] = A[M,128] @ W[128,128] + bias ----------------
// A as bf16 hi/lo (row-major), W transposed bf16 hi/lo [N][K].
// D = Ahi@Whi + Ahi@Wlo + Alo@Whi (fp32 accum). Fused column sum/sumsq atomics.
#define KC 64
#define SM_AH 0
#define SM_AL 16384
#define SM_WH 32768
#define SM_WL 49152
#define SM_TOTAL 65536

__global__ __launch_bounds__(256, 2) void mma_gemm_kernel(
    const __nv_bfloat16* __restrict__ Ahi, const __nv_bfloat16* __restrict__ Alo,
    const __nv_bfloat16* __restrict__ Whi, const __nv_bfloat16* __restrict__ Wlo,
    const float* __restrict__ bias, float* __restrict__ Cout,
    float* __restrict__ stats) {
    extern __shared__ char smem[];
    uint32_t sb = smem_u32(smem);
    int tid = threadIdx.x, wid = tid >> 5, lane = tid & 31;
    int wm = wid >> 2, wn = wid & 3;
    int row0 = blockIdx.x * 128;

    float acc[4][4][4];
    #pragma unroll
    for (int i = 0; i < 4; i++)
        #pragma unroll
        for (int j = 0; j < 4; j++)
            #pragma unroll
            for (int k = 0; k < 4; k++) acc[i][j][k] = 0.f;

    // fragment smem addresses (lane-dependent base pattern, c8 added per k-step)
    int frow = ((lane >> 3) & 1) * 8 + (lane & 7);
    int fc8base = (lane >> 4);  // 0 or 1

    for (int kc = 0; kc < DD; kc += KC) {
        // ---- load tiles into swizzled smem ----
        #pragma unroll
        for (int it = 0; it < 4; it++) {
            int idx = it * 256 + tid;      // 0..1023
            int row = idx >> 3, c8 = idx & 7;
            uint32_t d = sw(row, c8);
            int gr = row0 + row;
            uint4 vh = make_uint4(0u, 0u, 0u, 0u), vl = vh;
            if (gr < N_NODES) {
                vh = *(const uint4*)(Ahi + (size_t)gr * DD + kc + c8 * 8);
                vl = *(const uint4*)(Alo + (size_t)gr * DD + kc + c8 * 8);
            }
            *(uint4*)(smem + SM_AH + d) = vh;
            *(uint4*)(smem + SM_AL + d) = vl;
            uint4 wh = *(const uint4*)(Whi + (size_t)row * DD + kc + c8 * 8);
            uint4 wl = *(const uint4*)(Wlo + (size_t)row * DD + kc + c8 * 8);
            *(uint4*)(smem + SM_WH + d) = wh;
            *(uint4*)(smem + SM_WL + d) = wl;
        }
        __syncthreads();

        #pragma unroll
        for (int ks = 0; ks < KC / 16; ks++) {
            int c8 = ks * 2 + fc8base;
            // B fragments: 4 n-tiles of 8, hi and lo
            uint32_t bh[4][2], bl[4][2];
            #pragma unroll
            for (int np = 0; np < 2; np++) {
                int n = wn * 32 + np * 16 + frow;
                uint32_t t[4];
                ldm4(t, sb + SM_WH + sw(n, c8));
                bh[np * 2 + 0][0] = t[0]; bh[np * 2 + 1][0] = t[1];
                bh[np * 2 + 0][1] = t[2]; bh[np * 2 + 1][1] = t[3];
                ldm4(t, sb + SM_WL + sw(n, c8));
                bl[np * 2 + 0][0] = t[0]; bl[np * 2 + 1][0] = t[1];
                bl[np * 2 + 0][1] = t[2]; bl[np * 2 + 1][1] = t[3];
            }
            #pragma unroll
            for (int mt = 0; mt < 4; mt++) {
                int r = wm * 64 + mt * 16 + frow;
                uint32_t ah[4], al[4];
                ldm4(ah, sb + SM_AH + sw(r, c8));
                ldm4(al, sb + SM_AL + sw(r, c8));
                #pragma unroll
                for (int nt = 0; nt < 4; nt++) {
                    mma16816(acc[mt][nt], ah, bh[nt]);
                    mma16816(acc[mt][nt], ah, bl[nt]);
                    mma16816(acc[mt][nt], al, bh[nt]);
                }
            }
        }
        __syncthreads();
    }

    // ---- epilogue: bias, store, fused column stats ----
    float st[4][4];  // per n-tile: {sum.x, sum.y, sq.x, sq.y}
    #pragma unroll
    for (int nt = 0; nt < 4; nt++)
        #pragma unroll
        for (int k = 0; k < 4; k++) st[nt][k] = 0.f;

    #pragma unroll
    for (int nt = 0; nt < 4; nt++) {
        int col = wn * 32 + nt * 8 + (lane & 3) * 2;
        float2 bs = *(const float2*)(bias + col);
        #pragma unroll
        for (int mt = 0; mt < 4; mt++) {
            int r0g = row0 + wm * 64 + mt * 16 + (lane >> 2);
            float v0 = acc[mt][nt][0] + bs.x;
            float v1 = acc[mt][nt][1] + bs.y;
            float v2 = acc[mt][nt][2] + bs.x;
            float v3 = acc[mt][nt][3] + bs.y;
            if (r0g < N_NODES) {
                *(float2*)(Cout + (size_t)r0g * DD + col) = make_float2(v0, v1);
                st[nt][0] += v0; st[nt][1] += v1;
                st[nt][2] = fmaf(v0, v0, st[nt][2]);
                st[nt][3] = fmaf(v1, v1, st[nt][3]);
            }
            if (r0g + 8 < N_NODES) {
                *(float2*)(Cout + (size_t)(r0g + 8) * DD + col) = make_float2(v2, v3);
                st[nt][0] += v2; st[nt][1] += v3;
                st[nt][2] = fmaf(v2, v2, st[nt][2]);
                st[nt][3] = fmaf(v3, v3, st[nt][3]);
            }
        }
    }
    // reduce over lanes sharing the same (lane & 3)
    #pragma unroll
    for (int nt = 0; nt < 4; nt++) {
        #pragma unroll
        for (int off = 4; off < 32; off <<= 1) {
            #pragma unroll
            for (int k = 0; k < 4; k++)
                st[nt][k] += __shfl_xor_sync(0xffffffffu, st[nt][k], off);
        }
    }
    if (lane < 4) {
        #pragma unroll
        for (int nt = 0; nt < 4; nt++) {
            int col = wn * 32 + nt * 8 + lane * 2;
            atomicAdd(stats + col,          st[nt][0]);
            atomicAdd(stats + col + 1,      st[nt][1]);
            atomicAdd(stats + DD + col,     st[nt][2]);
            atomicAdd(stats + DD + col + 1, st[nt][3]);
        }
    }
}

// ---------------- BN finalize ----------------
__global__ void bn_finalize(const float* __restrict__ stats, const float* __restrict__ g,
                            const float* __restrict__ beta, float* __restrict__ ss) {
    int c = threadIdx.x;
    const float invN = 1.0f / (float)N_NODES;
    float mean = stats[c] * invN;
    float var = stats[DD + c] * invN - mean * mean;
    float rstd = rsqrtf(var + BN_EPS);
    float scale = __ldg(g + c) * rstd;
    ss[c] = scale;
    ss[DD + c] = __ldg(beta + c) - scale * mean;
}

// ---------------- BN1 apply + ReLU + bf16 split (GEMM2 input) ----------------
__global__ void bnsplit_kernel(const float* __restrict__ z, const float* __restrict__ ss,
                               __nv_bfloat16* __restrict__ ohi, __nv_bfloat16* __restrict__ olo) {
    int idx = blockIdx.x * blockDim.x + threadIdx.x;   // float4 index
    if (idx >= N_NODES * 32) return;
    int col4 = (idx & 31) * 4;
    float4 v = *(const float4*)(z + (size_t)idx * 4);
    float4 sc = *(const float4*)(ss + col4);
    float4 sh = *(const float4*)(ss + DD + col4);
    float r0 = fmaxf(0.f, fmaf(sc.x, v.x, sh.x));
    float r1 = fmaxf(0.f, fmaf(sc.y, v.y, sh.y));
    float r2 = fmaxf(0.f, fmaf(sc.z, v.z, sh.z));
    float r3 = fmaxf(0.f, fmaf(sc.w, v.w, sh.w));
    __nv_bfloat16 h0 = __float2bfloat16(r0), h1 = __float2bfloat16(r1);
    __nv_bfloat16 h2 = __float2bfloat16(r2), h3 = __float2bfloat16(r3);
    __nv_bfloat162 hi01, hi23, lo01, lo23;
    hi01.x = h0; hi01.y = h1; hi23.x = h2; hi23.y = h3;
    lo01.x = __float2bfloat16(r0 - __bfloat162float(h0));
    lo01.y = __float2bfloat16(r1 - __bfloat162float(h1));
    lo23.x = __float2bfloat16(r2 - __bfloat162float(h2));
    lo23.y = __float2bfloat16(r3 - __bfloat162float(h3));
    uint2 hp, lp;
    hp.x = *(uint32_t*)&hi01; hp.y = *(uint32_t*)&hi23;
    lp.x = *(uint32_t*)&lo01; lp.y = *(uint32_t*)&lo23;
    *(uint2*)(ohi + (size_t)idx * 4) = hp;
    *(uint2*)(olo + (size_t)idx * 4) = lp;
}

// ---------------- BN2+ReLU apply + per-graph pooling (graph_ids sorted) ----------------
__global__ void apply_pool_kernel(const float* __restrict__ z, const float* __restrict__ ss,
                                  const int* __restrict__ gid, float* __restrict__ h,
                                  float* __restrict__ gp) {
    int tid = threadIdx.x;  // 128
    int r0 = blockIdx.x * APPLY_ROWS;
    if (r0 >= N_NODES) return;
    int rend = min(r0 + APPLY_ROWS, N_NODES);
    float sc = __ldg(ss + tid), sh = __ldg(ss + DD + tid);
    float acc = 0.f;
    int curg = __ldg(gid + r0);
    for (int r = r0; r < rend; r++) {
        float v = z[(size_t)r * DD + tid];
        float hv = fmaxf(0.f, fmaf(sc, v, sh));
        h[(size_t)r * DD + tid] = hv;
        int g = __ldg(gid + r);
        if (g != curg) {
            atomicAdd(gp + (size_t)curg * DD + tid, acc);
            acc = 0.f;
            curg = g;
        }
        acc += hv;
    }
    atomicAdd(gp + (size_t)curg * DD + tid, acc);
}

__global__ void pool_x_kernel(const float* __restrict__ x, const int* __restrict__ gid,
                              float* __restrict__ gp) {
    int tid = threadIdx.x;
    int r0 = blockIdx.x * APPLY_ROWS;
    if (r0 >= N_NODES) return;
    int rend = min(r0 + APPLY_ROWS, N_NODES);
    float acc = 0.f;
    int curg = __ldg(gid + r0);
    for (int r = r0; r < rend; r++) {
        float v = x[(size_t)r * DD + tid];
        int g = __ldg(gid + r);
        if (g != curg) {
            atomicAdd(gp + (size_t)curg * DD + tid, acc);
            acc = 0.f;
            curg = g;
        }
        acc += v;
    }
    atomicAdd(gp + (size_t)curg * DD + tid, acc);
}

// ---------------- readout ----------------
__global__ void readout_kernel(const float* __restrict__ gp, const float* __restrict__ Wp,
                               const float* __restrict__ bp, float* __restrict__ out) {
    int g = blockIdx.x;
    int tid = threadIdx.x;  // 128
    int lane = tid & 31, warp = tid >> 5;
    float partial[CC];
    #pragma unroll
    for (int c = 0; c < CC; c++) partial[c] = 0.f;
    for (int l = 0; l < 5; l++) {
        float v = gp[((size_t)l * GG + g) * DD + tid];
        const float* w = Wp + ((size_t)l * DD + tid) * CC;
        #pragma unroll
        for (int c = 0; c < CC; c++) partial[c] = fmaf(v, __ldg(w + c), partial[c]);
    }
    __shared__ float red[4][CC];
    #pragma unroll
    for (int c = 0; c < CC; c++) {
        float v = partial[c];
        #pragma unroll
        for (int off = 16; off; off >>= 1) v += __shfl_down_sync(0xffffffffu, v, off);
        if (lane == 0) red[warp][c] = v;
    }
    __syncthreads();
    if (tid < CC) {
        float s = red[0][tid] + red[1][tid] + red[2][tid] + red[3][tid];
        float b = 0.f;
        #pragma unroll
        for (int l = 0; l < 5; l++) b += __ldg(bp + l * CC + tid);
        out[g * CC + tid] = s + b;
    }
}

// ---------------- host orchestration ----------------
extern "C" void kernel_launch(void* const* d_in, const int* in_sizes, int n_in,
                              void* d_out, int out_size) {
    const float* x     = (const float*)d_in[0];
    const float* eps   = (const float*)d_in[1];
    const float* W1    = (const float*)d_in[2];
    const float* b1    = (const float*)d_in[3];
    const float* g1    = (const float*)d_in[4];
    const float* beta1 = (const float*)d_in[5];
    const float* W2    = (const float*)d_in[6];
    const float* b2    = (const float*)d_in[7];
    const float* g2    = (const float*)d_in[8];
    const float* beta2 = (const float*)d_in[9];
    const float* Wp    = (const float*)d_in[10];
    const float* bp    = (const float*)d_in[11];
    const int* esrc    = (const int*)d_in[12];
    const int* edst    = (const int*)d_in[13];
    const int* gid     = (const int*)d_in[14];
    float* out = (float*)d_out;

    float *hbuf, *z1, *z2, *gp, *stats, *ssbuf;
    __nv_bfloat16 *ahi, *alo, *whi, *wlo;
    int *counts, *rowptr, *cursor, *srcsorted;
    cudaGetSymbolAddress((void**)&hbuf, g_h);
    cudaGetSymbolAddress((void**)&z1, g_z1);
    cudaGetSymbolAddress((void**)&z2, g_z2);
    cudaGetSymbolAddress((void**)&ahi, g_ahi);
    cudaGetSymbolAddress((void**)&alo, g_alo);
    cudaGetSymbolAddress((void**)&whi, g_whi);
    cudaGetSymbolAddress((void**)&wlo, g_wlo);
    cudaGetSymbolAddress((void**)&gp, g_gp);
    cudaGetSymbolAddress((void**)&stats, g_stats);
    cudaGetSymbolAddress((void**)&ssbuf, g_ss);
    cudaGetSymbolAddress((void**)&counts, g_counts);
    cudaGetSymbolAddress((void**)&rowptr, g_rowptr);
    cudaGetSymbolAddress((void**)&cursor, g_cursor);
    cudaGetSymbolAddress((void**)&srcsorted, g_srcsorted);

    cudaFuncSetAttribute(mma_gemm_kernel, cudaFuncAttributeMaxDynamicSharedMemorySize, SM_TOTAL);

    zero_kernel<<<256, 256>>>(gp, 5 * GG * DD, stats, NLAYERS * 2 * 2 * DD, counts, N_NODES);
    wprep_kernel<<<dim3(8, 8), 128>>>(W1, W2, whi, wlo);
    count_kernel<<<(E_EDGES + 255) / 256, 256>>>(edst, counts);
    scan_kernel<<<1, 1024>>>(counts, rowptr, cursor);
    fill_kernel<<<(E_EDGES + 255) / 256, 256>>>(esrc, edst, cursor, srcsorted);
    pool_x_kernel<<<(N_NODES + APPLY_ROWS - 1) / APPLY_ROWS, 128>>>(x, gid, gp);

    const float* h = x;
    for (int l = 0; l < NLAYERS; l++) {
        float* st1 = stats + (l * 2 + 0) * 2 * DD;
        float* st2 = stats + (l * 2 + 1) * 2 * DD;
        float* ss1 = ssbuf + (l * 2 + 0) * 2 * DD;
        float* ss2 = ssbuf + (l * 2 + 1) * 2 * DD;

        spmm_split_kernel<<<N_NODES, 128>>>(h, rowptr, srcsorted, eps, l, ahi, alo);
        mma_gemm_kernel<<<MTILES, 256, SM_TOTAL>>>(
            ahi, alo, whi + (size_t)l * DD * DD, wlo + (size_t)l * DD * DD,
            b1 + l * DD, z1, st1);
        bn_finalize<<<1, DD>>>(st1, g1 + l * DD, beta1 + l * DD, ss1);
        bnsplit_kernel<<<(N_NODES * 32 + 255) / 256, 256>>>(z1, ss1, ahi, alo);
        mma_gemm_kernel<<<MTILES, 256, SM_TOTAL>>>(
            ahi, alo, whi + (size_t)(4 + l) * DD * DD, wlo + (size_t)(4 + l) * DD * DD,
            b2 + l * DD, z2, st2);
        bn_finalize<<<1, DD>>>(st2, g2 + l * DD, beta2 + l * DD, ss2);
        apply_pool_kernel<<<(N_NODES + APPLY_ROWS - 1) / APPLY_ROWS, 128>>>(
            z2, ss2, gid, hbuf, gp + (size_t)(l + 1) * GG * DD);
        h = hbuf;
    }
    readout_kernel<<<GG, 128>>>(gp, Wp, bp, out);
}

// round 4
// speedup vs baseline: 1.6046x; 1.0605x over previous
#include <cuda_runtime.h>
#include <cuda_bf16.h>
#include <cstdint>

#define N_NODES 50000
#define E_EDGES 800000
#define DD 128
#define GG 256
#define CC 16
#define NLAYERS 4   // L-1 GIN layers
#define BN_EPS 1e-5f
#define APPLY_ROWS 64
#define MTILES ((N_NODES + 127) / 128)   // 391
#define SCAN_BLOCKS ((N_NODES + 1023) / 1024)  // 49

// ---------------- device scratch (no allocation allowed) ----------------
__device__ float g_h [(size_t)N_NODES * DD];    // hidden (fp32)
__device__ float g_z1[(size_t)N_NODES * DD];    // z1 (pre-BN1)
__device__ float g_z2[(size_t)N_NODES * DD];    // z2 (pre-BN2)
__device__ __nv_bfloat16 g_ahi[(size_t)N_NODES * DD];  // GEMM A operand hi
__device__ __nv_bfloat16 g_alo[(size_t)N_NODES * DD];  // GEMM A operand lo
__device__ __nv_bfloat16 g_whi[8 * DD * DD];    // transposed split weights [n][k]
__device__ __nv_bfloat16 g_wlo[8 * DD * DD];
__device__ float g_gp[5 * GG * DD];             // per-layer graph pools
__device__ float g_stats[NLAYERS * 2 * 2 * DD]; // sums / sumsq per (layer,bn)
__device__ int   g_counts[N_NODES];
__device__ int   g_rowptr[N_NODES + 1];
__device__ int   g_cursor[N_NODES];
__device__ int   g_srcsorted[E_EDGES];
__device__ int   g_blocksums[SCAN_BLOCKS];

// ================= warp-MMA helpers (portable, sm_80+) =================
__device__ __forceinline__ uint32_t smem_u32(const void* p) {
    uint32_t a;
    asm("{ .reg .u64 t; cvta.to.shared.u64 t, %1; cvt.u32.u64 %0, t; }" : "=r"(a) : "l"(p));
    return a;
}
__device__ __forceinline__ void ldm4(uint32_t* r, uint32_t addr) {
    asm volatile("ldmatrix.sync.aligned.m8n8.x4.shared.b16 {%0,%1,%2,%3}, [%4];"
        : "=r"(r[0]), "=r"(r[1]), "=r"(r[2]), "=r"(r[3]) : "r"(addr));
}
__device__ __forceinline__ void mma16816(float* d, const uint32_t* a, const uint32_t* b) {
    asm volatile("mma.sync.aligned.m16n8k16.row.col.f32.bf16.bf16.f32 "
        "{%0,%1,%2,%3}, {%4,%5,%6,%7}, {%8,%9}, {%0,%1,%2,%3};"
        : "+f"(d[0]), "+f"(d[1]), "+f"(d[2]), "+f"(d[3])
        : "r"(a[0]), "r"(a[1]), "r"(a[2]), "r"(a[3]), "r"(b[0]), "r"(b[1]));
}
// swizzled byte offset within a [128 rows x 64 bf16] tile (row = 128 B = 8 x 16B chunks)
__device__ __forceinline__ uint32_t sw(int row, int c8) {
    return (uint32_t)(row * 128 + ((c8 ^ (row & 7)) * 16));
}

// ---------------- utility: zero scratch ----------------
__global__ void zero_kernel(float* a, int na, float* b, int nb, int* c, int nc) {
    int i = blockIdx.x * blockDim.x + threadIdx.x;
    int stride = gridDim.x * blockDim.x;
    for (int j = i; j < na; j += stride) a[j] = 0.f;
    for (int j = i; j < nb; j += stride) b[j] = 0.f;
    for (int j = i; j < nc; j += stride) c[j] = 0;
}

// ---------------- CSR build ----------------
__global__ void count_kernel(const int* __restrict__ edst, int* counts) {
    int e = blockIdx.x * blockDim.x + threadIdx.x;
    if (e < E_EDGES) atomicAdd(&counts[edst[e]], 1);
}

// phase 1: per-1024-chunk block sums (256 threads x int4)
__global__ void scan_pass1(const int* __restrict__ counts, int* __restrict__ blocksums) {
    __shared__ int ws[8];
    int tid = threadIdx.x, lane = tid & 31, warp = tid >> 5;
    int base = blockIdx.x * 1024 + tid * 4;
    int4 v = make_int4(0, 0, 0, 0);
    if (base < N_NODES) v = *(const int4*)(counts + base);   // N_NODES % 4 == 0
    int s = v.x + v.y + v.z + v.w;
    #pragma unroll
    for (int off = 16; off; off >>= 1) s += __shfl_xor_sync(0xffffffffu, s, off);
    if (lane == 0) ws[warp] = s;
    __syncthreads();
    if (tid == 0) {
        int t = 0;
        #pragma unroll
        for (int w = 0; w < 8; w++) t += ws[w];
        blocksums[blockIdx.x] = t;
    }
}

// phase 2: exclusive scan of the 49 block sums (single thread, tiny)
__global__ void scan_pass2(int* __restrict__ blocksums, int* __restrict__ rowptr) {
    int run = 0;
    for (int i = 0; i < SCAN_BLOCKS; i++) {
        int v = blocksums[i];
        blocksums[i] = run;
        run += v;
    }
    rowptr[N_NODES] = run;
}

// phase 3: per-chunk local exclusive scan + block offset -> rowptr & cursor
__global__ void scan_pass3(const int* __restrict__ counts, const int* __restrict__ blocksums,
                           int* __restrict__ rowptr, int* __restrict__ cursor) {
    __shared__ int ws[8];
    int tid = threadIdx.x, lane = tid & 31, warp = tid >> 5;
    int base = blockIdx.x * 1024 + tid * 4;
    int4 v = make_int4(0, 0, 0, 0);
    if (base < N_NODES) v = *(const int4*)(counts + base);
    int t = v.x + v.y + v.z + v.w;
    int x = t;
    #pragma unroll
    for (int off = 1; off < 32; off <<= 1) {
        int y = __shfl_up_sync(0xffffffffu, x, off);
        if (lane >= off) x += y;
    }
    if (lane == 31) ws[warp] = x;
    __syncthreads();
    if (warp == 0 && lane < 8) {
        int s = ws[lane];
        #pragma unroll
        for (int off = 1; off < 8; off <<= 1) {
            int y = __shfl_up_sync(0x000000ffu, s, off);
            if (lane >= off) s += y;
        }
        ws[lane] = s;
    }
    __syncthreads();
    int excl = (x - t) + (warp ? ws[warp - 1] : 0) + blocksums[blockIdx.x];
    if (base < N_NODES) {
        int4 rp;
        rp.x = excl;
        rp.y = excl + v.x;
        rp.z = rp.y + v.y;
        rp.w = rp.z + v.z;
        *(int4*)(rowptr + base) = rp;
        *(int4*)(cursor + base) = rp;
    }
}

__global__ void fill_kernel(const int* __restrict__ esrc, const int* __restrict__ edst,
                            int* cursor, int* srcsorted) {
    int e = blockIdx.x * blockDim.x + threadIdx.x;
    if (e < E_EDGES) {
        int pos = atomicAdd(&cursor[edst[e]], 1);
        srcsorted[pos] = esrc[e];
    }
}

// ---------------- weight prep: transpose + bf16 hi/lo split ----------------
__global__ void wprep_kernel(const float* __restrict__ W1, const float* __restrict__ W2,
                             __nv_bfloat16* __restrict__ whi, __nv_bfloat16* __restrict__ wlo) {
    int m = blockIdx.x;
    int kb = blockIdx.y;
    int n = threadIdx.x;
    const float* W = (m < 4) ? (W1 + (size_t)m * DD * DD) : (W2 + (size_t)(m - 4) * DD * DD);
    for (int k = kb * 16; k < kb * 16 + 16; k++) {
        float w = W[(size_t)k * DD + n];
        __nv_bfloat16 h16 = __float2bfloat16(w);
        float hif = __bfloat162float(h16);
        size_t o = ((size_t)m * DD + n) * DD + k;
        whi[o] = h16;
        wlo[o] = __float2bfloat16(w - hif);
    }
}

// ---------------- SpMM + eps + bf16 split ----------------
__global__ void spmm_split_kernel(const float* __restrict__ h, const int* __restrict__ rowptr,
                                  const int* __restrict__ srcs, const float* __restrict__ eps,
                                  int l, __nv_bfloat16* __restrict__ ohi,
                                  __nv_bfloat16* __restrict__ olo) {
    int node = blockIdx.x;
    int tid = threadIdx.x;  // 128
    float scale = 1.0f + __ldg(eps + l);
    float acc = scale * __ldg(h + (size_t)node * DD + tid);
    int s = __ldg(rowptr + node), e = __ldg(rowptr + node + 1);
    int i = s;
    for (; i + 3 < e; i += 4) {
        int s0 = __ldg(srcs + i + 0);
        int s1 = __ldg(srcs + i + 1);
        int s2 = __ldg(srcs + i + 2);
        int s3 = __ldg(srcs + i + 3);
        acc += __ldg(h + (size_t)s0 * DD + tid) + __ldg(h + (size_t)s1 * DD + tid)
             + __ldg(h + (size_t)s2 * DD + tid) + __ldg(h + (size_t)s3 * DD + tid);
    }
    for (; i < e; i++) acc += __ldg(h + (size_t)__ldg(srcs + i) * DD + tid);
    __nv_bfloat16 h16 = __float2bfloat16(acc);
    float hif = __bfloat162float(h16);
    size_t o = (size_t)node * DD + tid;
    ohi[o] = h16;
    olo[o] = __float2bfloat16(acc - hif);
}

// ---------------- HMMA GEMM: C[M,128] = A[M,128] @ W[128,128] + bias ----------------
#define KC 64
#define SM_AH 0
#define SM_AL 16384
#define SM_WH 32768
#define SM_WL 49152
#define SM_TOTAL 65536

__global__ __launch_bounds__(256, 2) void mma_gemm_kernel(
    const __nv_bfloat16* __restrict__ Ahi, const __nv_bfloat16* __restrict__ Alo,
    const __nv_bfloat16* __restrict__ Whi, const __nv_bfloat16* __restrict__ Wlo,
    const float* __restrict__ bias, float* __restrict__ Cout,
    float* __restrict__ stats) {
    extern __shared__ char smem[];
    uint32_t sb = smem_u32(smem);
    int tid = threadIdx.x, wid = tid >> 5, lane = tid & 31;
    int wm = wid >> 2, wn = wid & 3;
    int row0 = blockIdx.x * 128;

    float acc[4][4][4];
    #pragma unroll
    for (int i = 0; i < 4; i++)
        #pragma unroll
        for (int j = 0; j < 4; j++)
            #pragma unroll
            for (int k = 0; k < 4; k++) acc[i][j][k] = 0.f;

    int frow = ((lane >> 3) & 1) * 8 + (lane & 7);
    int fc8base = (lane >> 4);  // 0 or 1

    for (int kc = 0; kc < DD; kc += KC) {
        #pragma unroll
        for (int it = 0; it < 4; it++) {
            int idx = it * 256 + tid;      // 0..1023
            int row = idx >> 3, c8 = idx & 7;
            uint32_t d = sw(row, c8);
            int gr = row0 + row;
            uint4 vh = make_uint4(0u, 0u, 0u, 0u), vl = vh;
            if (gr < N_NODES) {
                vh = *(const uint4*)(Ahi + (size_t)gr * DD + kc + c8 * 8);
                vl = *(const uint4*)(Alo + (size_t)gr * DD + kc + c8 * 8);
            }
            *(uint4*)(smem + SM_AH + d) = vh;
            *(uint4*)(smem + SM_AL + d) = vl;
            uint4 wh = *(const uint4*)(Whi + (size_t)row * DD + kc + c8 * 8);
            uint4 wl = *(const uint4*)(Wlo + (size_t)row * DD + kc + c8 * 8);
            *(uint4*)(smem + SM_WH + d) = wh;
            *(uint4*)(smem + SM_WL + d) = wl;
        }
        __syncthreads();

        #pragma unroll
        for (int ks = 0; ks < KC / 16; ks++) {
            int c8 = ks * 2 + fc8base;
            uint32_t bh[4][2], bl[4][2];
            #pragma unroll
            for (int np = 0; np < 2; np++) {
                int n = wn * 32 + np * 16 + frow;
                uint32_t t[4];
                ldm4(t, sb + SM_WH + sw(n, c8));
                bh[np * 2 + 0][0] = t[0]; bh[np * 2 + 1][0] = t[1];
                bh[np * 2 + 0][1] = t[2]; bh[np * 2 + 1][1] = t[3];
                ldm4(t, sb + SM_WL + sw(n, c8));
                bl[np * 2 + 0][0] = t[0]; bl[np * 2 + 1][0] = t[1];
                bl[np * 2 + 0][1] = t[2]; bl[np * 2 + 1][1] = t[3];
            }
            #pragma unroll
            for (int mt = 0; mt < 4; mt++) {
                int r = wm * 64 + mt * 16 + frow;
                uint32_t ah[4], al[4];
                ldm4(ah, sb + SM_AH + sw(r, c8));
                ldm4(al, sb + SM_AL + sw(r, c8));
                #pragma unroll
                for (int nt = 0; nt < 4; nt++) {
                    mma16816(acc[mt][nt], ah, bh[nt]);
                    mma16816(acc[mt][nt], ah, bl[nt]);
                    mma16816(acc[mt][nt], al, bh[nt]);
                }
            }
        }
        __syncthreads();
    }

    // ---- epilogue: bias, store, fused column stats ----
    float st[4][4];
    #pragma unroll
    for (int nt = 0; nt < 4; nt++)
        #pragma unroll
        for (int k = 0; k < 4; k++) st[nt][k] = 0.f;

    #pragma unroll
    for (int nt = 0; nt < 4; nt++) {
        int col = wn * 32 + nt * 8 + (lane & 3) * 2;
        float2 bs = *(const float2*)(bias + col);
        #pragma unroll
        for (int mt = 0; mt < 4; mt++) {
            int r0g = row0 + wm * 64 + mt * 16 + (lane >> 2);
            float v0 = acc[mt][nt][0] + bs.x;
            float v1 = acc[mt][nt][1] + bs.y;
            float v2 = acc[mt][nt][2] + bs.x;
            float v3 = acc[mt][nt][3] + bs.y;
            if (r0g < N_NODES) {
                *(float2*)(Cout + (size_t)r0g * DD + col) = make_float2(v0, v1);
                st[nt][0] += v0; st[nt][1] += v1;
                st[nt][2] = fmaf(v0, v0, st[nt][2]);
                st[nt][3] = fmaf(v1, v1, st[nt][3]);
            }
            if (r0g + 8 < N_NODES) {
                *(float2*)(Cout + (size_t)(r0g + 8) * DD + col) = make_float2(v2, v3);
                st[nt][0] += v2; st[nt][1] += v3;
                st[nt][2] = fmaf(v2, v2, st[nt][2]);
                st[nt][3] = fmaf(v3, v3, st[nt][3]);
            }
        }
    }
    #pragma unroll
    for (int nt = 0; nt < 4; nt++) {
        #pragma unroll
        for (int off = 4; off < 32; off <<= 1) {
            #pragma unroll
            for (int k = 0; k < 4; k++)
                st[nt][k] += __shfl_xor_sync(0xffffffffu, st[nt][k], off);
        }
    }
    if (lane < 4) {
        #pragma unroll
        for (int nt = 0; nt < 4; nt++) {
            int col = wn * 32 + nt * 8 + lane * 2;
            atomicAdd(stats + col,          st[nt][0]);
            atomicAdd(stats + col + 1,      st[nt][1]);
            atomicAdd(stats + DD + col,     st[nt][2]);
            atomicAdd(stats + DD + col + 1, st[nt][3]);
        }
    }
}

// ---------------- BN1 apply (inline finalize) + ReLU + bf16 split ----------------
__global__ void bnsplit_kernel(const float* __restrict__ z, const float* __restrict__ stats,
                               const float* __restrict__ g, const float* __restrict__ beta,
                               __nv_bfloat16* __restrict__ ohi, __nv_bfloat16* __restrict__ olo) {
    int idx = blockIdx.x * blockDim.x + threadIdx.x;   // float4 index
    if (idx >= N_NODES * 32) return;
    int col4 = (idx & 31) * 4;
    const float invN = 1.0f / (float)N_NODES;
    float4 sm = *(const float4*)(stats + col4);
    float4 sq = *(const float4*)(stats + DD + col4);
    float4 gg = *(const float4*)(g + col4);
    float4 bb = *(const float4*)(beta + col4);
    float m0 = sm.x * invN, m1 = sm.y * invN, m2 = sm.z * invN, m3 = sm.w * invN;
    float s0 = gg.x * rsqrtf(sq.x * invN - m0 * m0 + BN_EPS);
    float s1 = gg.y * rsqrtf(sq.y * invN - m1 * m1 + BN_EPS);
    float s2 = gg.z * rsqrtf(sq.z * invN - m2 * m2 + BN_EPS);
    float s3 = gg.w * rsqrtf(sq.w * invN - m3 * m3 + BN_EPS);
    float t0 = bb.x - s0 * m0, t1 = bb.y - s1 * m1;
    float t2 = bb.z - s2 * m2, t3 = bb.w - s3 * m3;
    float4 v = *(const float4*)(z + (size_t)idx * 4);
    float r0 = fmaxf(0.f, fmaf(s0, v.x, t0));
    float r1 = fmaxf(0.f, fmaf(s1, v.y, t1));
    float r2 = fmaxf(0.f, fmaf(s2, v.z, t2));
    float r3 = fmaxf(0.f, fmaf(s3, v.w, t3));
    __nv_bfloat16 h0 = __float2bfloat16(r0), h1 = __float2bfloat16(r1);
    __nv_bfloat16 h2 = __float2bfloat16(r2), h3 = __float2bfloat16(r3);
    __nv_bfloat162 hi01, hi23, lo01, lo23;
    hi01.x = h0; hi01.y = h1; hi23.x = h2; hi23.y = h3;
    lo01.x = __float2bfloat16(r0 - __bfloat162float(h0));
    lo01.y = __float2bfloat16(r1 - __bfloat162float(h1));
    lo23.x = __float2bfloat16(r2 - __bfloat162float(h2));
    lo23.y = __float2bfloat16(r3 - __bfloat162float(h3));
    uint2 hp, lp;
    hp.x = *(uint32_t*)&hi01; hp.y = *(uint32_t*)&hi23;
    lp.x = *(uint32_t*)&lo01; lp.y = *(uint32_t*)&lo23;
    *(uint2*)(ohi + (size_t)idx * 4) = hp;
    *(uint2*)(olo + (size_t)idx * 4) = lp;
}

// ---------------- BN2 (inline finalize) + ReLU + per-graph pooling ----------------
__global__ void apply_pool_kernel(const float* __restrict__ z, const float* __restrict__ stats,
                                  const float* __restrict__ g, const float* __restrict__ beta,
                                  const int* __restrict__ gid, float* __restrict__ h,
                                  float* __restrict__ gp) {
    int tid = threadIdx.x;  // 128
    int r0 = blockIdx.x * APPLY_ROWS;
    if (r0 >= N_NODES) return;
    int rend = min(r0 + APPLY_ROWS, N_NODES);
    const float invN = 1.0f / (float)N_NODES;
    float mean = __ldg(stats + tid) * invN;
    float var = __ldg(stats + DD + tid) * invN - mean * mean;
    float sc = __ldg(g + tid) * rsqrtf(var + BN_EPS);
    float sh = __ldg(beta + tid) - sc * mean;
    float acc = 0.f;
    int curg = __ldg(gid + r0);
    for (int r = r0; r < rend; r++) {
        float v = z[(size_t)r * DD + tid];
        float hv = fmaxf(0.f, fmaf(sc, v, sh));
        h[(size_t)r * DD + tid] = hv;
        int gcur = __ldg(gid + r);
        if (gcur != curg) {
            atomicAdd(gp + (size_t)curg * DD + tid, acc);
            acc = 0.f;
            curg = gcur;
        }
        acc += hv;
    }
    atomicAdd(gp + (size_t)curg * DD + tid, acc);
}

__global__ void pool_x_kernel(const float* __restrict__ x, const int* __restrict__ gid,
                              float* __restrict__ gp) {
    int tid = threadIdx.x;
    int r0 = blockIdx.x * APPLY_ROWS;
    if (r0 >= N_NODES) return;
    int rend = min(r0 + APPLY_ROWS, N_NODES);
    float acc = 0.f;
    int curg = __ldg(gid + r0);
    for (int r = r0; r < rend; r++) {
        float v = x[(size_t)r * DD + tid];
        int gcur = __ldg(gid + r);
        if (gcur != curg) {
            atomicAdd(gp + (size_t)curg * DD + tid, acc);
            acc = 0.f;
            curg = gcur;
        }
        acc += v;
    }
    atomicAdd(gp + (size_t)curg * DD + tid, acc);
}

// ---------------- readout ----------------
__global__ void readout_kernel(const float* __restrict__ gp, const float* __restrict__ Wp,
                               const float* __restrict__ bp, float* __restrict__ out) {
    int g = blockIdx.x;
    int tid = threadIdx.x;  // 128
    int lane = tid & 31, warp = tid >> 5;
    float partial[CC];
    #pragma unroll
    for (int c = 0; c < CC; c++) partial[c] = 0.f;
    for (int l = 0; l < 5; l++) {
        float v = gp[((size_t)l * GG + g) * DD + tid];
        const float* w = Wp + ((size_t)l * DD + tid) * CC;
        #pragma unroll
        for (int c = 0; c < CC; c++) partial[c] = fmaf(v, __ldg(w + c), partial[c]);
    }
    __shared__ float red[4][CC];
    #pragma unroll
    for (int c = 0; c < CC; c++) {
        float v = partial[c];
        #pragma unroll
        for (int off = 16; off; off >>= 1) v += __shfl_down_sync(0xffffffffu, v, off);
        if (lane == 0) red[warp][c] = v;
    }
    __syncthreads();
    if (tid < CC) {
        float s = red[0][tid] + red[1][tid] + red[2][tid] + red[3][tid];
        float b = 0.f;
        #pragma unroll
        for (int l = 0; l < 5; l++) b += __ldg(bp + l * CC + tid);
        out[g * CC + tid] = s + b;
    }
}

// ---------------- host orchestration ----------------
extern "C" void kernel_launch(void* const* d_in, const int* in_sizes, int n_in,
                              void* d_out, int out_size) {
    const float* x     = (const float*)d_in[0];
    const float* eps   = (const float*)d_in[1];
    const float* W1    = (const float*)d_in[2];
    const float* b1    = (const float*)d_in[3];
    const float* g1    = (const float*)d_in[4];
    const float* beta1 = (const float*)d_in[5];
    const float* W2    = (const float*)d_in[6];
    const float* b2    = (const float*)d_in[7];
    const float* g2    = (const float*)d_in[8];
    const float* beta2 = (const float*)d_in[9];
    const float* Wp    = (const float*)d_in[10];
    const float* bp    = (const float*)d_in[11];
    const int* esrc    = (const int*)d_in[12];
    const int* edst    = (const int*)d_in[13];
    const int* gid     = (const int*)d_in[14];
    float* out = (float*)d_out;

    float *hbuf, *z1, *z2, *gp, *stats;
    __nv_bfloat16 *ahi, *alo, *whi, *wlo;
    int *counts, *rowptr, *cursor, *srcsorted, *blocksums;
    cudaGetSymbolAddress((void**)&hbuf, g_h);
    cudaGetSymbolAddress((void**)&z1, g_z1);
    cudaGetSymbolAddress((void**)&z2, g_z2);
    cudaGetSymbolAddress((void**)&ahi, g_ahi);
    cudaGetSymbolAddress((void**)&alo, g_alo);
    cudaGetSymbolAddress((void**)&whi, g_whi);
    cudaGetSymbolAddress((void**)&wlo, g_wlo);
    cudaGetSymbolAddress((void**)&gp, g_gp);
    cudaGetSymbolAddress((void**)&stats, g_stats);
    cudaGetSymbolAddress((void**)&counts, g_counts);
    cudaGetSymbolAddress((void**)&rowptr, g_rowptr);
    cudaGetSymbolAddress((void**)&cursor, g_cursor);
    cudaGetSymbolAddress((void**)&srcsorted, g_srcsorted);
    cudaGetSymbolAddress((void**)&blocksums, g_blocksums);

    cudaFuncSetAttribute(mma_gemm_kernel, cudaFuncAttributeMaxDynamicSharedMemorySize, SM_TOTAL);

    zero_kernel<<<256, 256>>>(gp, 5 * GG * DD, stats, NLAYERS * 2 * 2 * DD, counts, N_NODES);
    wprep_kernel<<<dim3(8, 8), 128>>>(W1, W2, whi, wlo);
    count_kernel<<<(E_EDGES + 255) / 256, 256>>>(edst, counts);
    scan_pass1<<<SCAN_BLOCKS, 256>>>(counts, blocksums);
    scan_pass2<<<1, 1>>>(blocksums, rowptr);
    scan_pass3<<<SCAN_BLOCKS, 256>>>(counts, blocksums, rowptr, cursor);
    fill_kernel<<<(E_EDGES + 255) / 256, 256>>>(esrc, edst, cursor, srcsorted);
    pool_x_kernel<<<(N_NODES + APPLY_ROWS - 1) / APPLY_ROWS, 128>>>(x, gid, gp);

    const float* h = x;
    for (int l = 0; l < NLAYERS; l++) {
        float* st1 = stats + (l * 2 + 0) * 2 * DD;
        float* st2 = stats + (l * 2 + 1) * 2 * DD;

        spmm_split_kernel<<<N_NODES, 128>>>(h, rowptr, srcsorted, eps, l, ahi, alo);
        mma_gemm_kernel<<<MTILES, 256, SM_TOTAL>>>(
            ahi, alo, whi + (size_t)l * DD * DD, wlo + (size_t)l * DD * DD,
            b1 + l * DD, z1, st1);
        bnsplit_kernel<<<(N_NODES * 32 + 255) / 256, 256>>>(
            z1, st1, g1 + l * DD, beta1 + l * DD, ahi, alo);
        mma_gemm_kernel<<<MTILES, 256, SM_TOTAL>>>(
            ahi, alo, whi + (size_t)(4 + l) * DD * DD, wlo + (size_t)(4 + l) * DD * DD,
            b2 + l * DD, z2, st2);
        apply_pool_kernel<<<(N_NODES + APPLY_ROWS - 1) / APPLY_ROWS, 128>>>(
            z2, st2, g2 + l * DD, beta2 + l * DD, gid, hbuf, gp + (size_t)(l + 1) * GG * DD);
        h = hbuf;
    }
    readout_kernel<<<GG, 128>>>(gp, Wp, bp, out);
}

// round 5
// speedup vs baseline: 1.6249x; 1.0127x over previous
#include <cuda_runtime.h>
#include <cuda_bf16.h>
#include <cstdint>

#define N_NODES 50000
#define E_EDGES 800000
#define DD 128
#define GG 256
#define CC 16
#define NLAYERS 4   // L-1 GIN layers
#define BN_EPS 1e-5f
#define APPLY_ROWS 64
#define MTILES ((N_NODES + 127) / 128)   // 391
#define SCAN_BLOCKS ((N_NODES + 1023) / 1024)  // 49

// ---------------- device scratch (no allocation allowed) ----------------
__device__ float g_h [(size_t)N_NODES * DD];     // hidden (fp32)
__device__ float g_pooled[(size_t)N_NODES * DD]; // spmm output
__device__ float g_z1[(size_t)N_NODES * DD];     // z1 (pre-BN1)
__device__ float g_z2[(size_t)N_NODES * DD];     // z2 (pre-BN2)
__device__ __nv_bfloat16 g_whi[8 * DD * DD];     // transposed split weights [n][k]
__device__ __nv_bfloat16 g_wlo[8 * DD * DD];
__device__ float g_gp[5 * GG * DD];              // per-layer graph pools
__device__ float g_stats[NLAYERS * 2 * 2 * DD];  // sums / sumsq per (layer,bn)
__device__ int   g_counts[N_NODES];
__device__ int   g_rowptr[N_NODES + 1];
__device__ int   g_cursor[N_NODES];
__device__ int   g_srcsorted[E_EDGES];
__device__ int   g_blocksums[SCAN_BLOCKS];

// ================= warp-MMA helpers (portable, sm_80+) =================
__device__ __forceinline__ uint32_t smem_u32(const void* p) {
    uint32_t a;
    asm("{ .reg .u64 t; cvta.to.shared.u64 t, %1; cvt.u32.u64 %0, t; }" : "=r"(a) : "l"(p));
    return a;
}
__device__ __forceinline__ void ldm4(uint32_t* r, uint32_t addr) {
    asm volatile("ldmatrix.sync.aligned.m8n8.x4.shared.b16 {%0,%1,%2,%3}, [%4];"
        : "=r"(r[0]), "=r"(r[1]), "=r"(r[2]), "=r"(r[3]) : "r"(addr));
}
__device__ __forceinline__ void mma16816(float* d, const uint32_t* a, const uint32_t* b) {
    asm volatile("mma.sync.aligned.m16n8k16.row.col.f32.bf16.bf16.f32 "
        "{%0,%1,%2,%3}, {%4,%5,%6,%7}, {%8,%9}, {%0,%1,%2,%3};"
        : "+f"(d[0]), "+f"(d[1]), "+f"(d[2]), "+f"(d[3])
        : "r"(a[0]), "r"(a[1]), "r"(a[2]), "r"(a[3]), "r"(b[0]), "r"(b[1]));
}
// swizzled byte offset within a [128 rows x 64 bf16] tile (row = 128 B = 8 x 16B chunks)
__device__ __forceinline__ uint32_t sw(int row, int c8) {
    return (uint32_t)(row * 128 + ((c8 ^ (row & 7)) * 16));
}
// split two fp32 into packed bf16x2 hi and lo (error-compensated)
__device__ __forceinline__ void split2(float a, float b, uint32_t& hi, uint32_t& lo) {
    __nv_bfloat162 h, l;
    h.x = __float2bfloat16(a); h.y = __float2bfloat16(b);
    l.x = __float2bfloat16(a - __bfloat162float(h.x));
    l.y = __float2bfloat16(b - __bfloat162float(h.y));
    hi = *(uint32_t*)&h; lo = *(uint32_t*)&l;
}

// ---------------- utility: zero scratch ----------------
__global__ void zero_kernel(float* a, int na, float* b, int nb, int* c, int nc) {
    int i = blockIdx.x * blockDim.x + threadIdx.x;
    int stride = gridDim.x * blockDim.x;
    for (int j = i; j < na; j += stride) a[j] = 0.f;
    for (int j = i; j < nb; j += stride) b[j] = 0.f;
    for (int j = i; j < nc; j += stride) c[j] = 0;
}

// ---------------- CSR build ----------------
__global__ void count_kernel(const int* __restrict__ edst, int* counts) {
    int e = blockIdx.x * blockDim.x + threadIdx.x;
    if (e < E_EDGES) atomicAdd(&counts[edst[e]], 1);
}

__global__ void scan_pass1(const int* __restrict__ counts, int* __restrict__ blocksums) {
    __shared__ int ws[8];
    int tid = threadIdx.x, lane = tid & 31, warp = tid >> 5;
    int base = blockIdx.x * 1024 + tid * 4;
    int4 v = make_int4(0, 0, 0, 0);
    if (base < N_NODES) v = *(const int4*)(counts + base);   // N_NODES % 4 == 0
    int s = v.x + v.y + v.z + v.w;
    #pragma unroll
    for (int off = 16; off; off >>= 1) s += __shfl_xor_sync(0xffffffffu, s, off);
    if (lane == 0) ws[warp] = s;
    __syncthreads();
    if (tid == 0) {
        int t = 0;
        #pragma unroll
        for (int w = 0; w < 8; w++) t += ws[w];
        blocksums[blockIdx.x] = t;
    }
}

__global__ void scan_pass2(int* __restrict__ blocksums, int* __restrict__ rowptr) {
    int run = 0;
    for (int i = 0; i < SCAN_BLOCKS; i++) {
        int v = blocksums[i];
        blocksums[i] = run;
        run += v;
    }
    rowptr[N_NODES] = run;
}

__global__ void scan_pass3(const int* __restrict__ counts, const int* __restrict__ blocksums,
                           int* __restrict__ rowptr, int* __restrict__ cursor) {
    __shared__ int ws[8];
    int tid = threadIdx.x, lane = tid & 31, warp = tid >> 5;
    int base = blockIdx.x * 1024 + tid * 4;
    int4 v = make_int4(0, 0, 0, 0);
    if (base < N_NODES) v = *(const int4*)(counts + base);
    int t = v.x + v.y + v.z + v.w;
    int x = t;
    #pragma unroll
    for (int off = 1; off < 32; off <<= 1) {
        int y = __shfl_up_sync(0xffffffffu, x, off);
        if (lane >= off) x += y;
    }
    if (lane == 31) ws[warp] = x;
    __syncthreads();
    if (warp == 0 && lane < 8) {
        int s = ws[lane];
        #pragma unroll
        for (int off = 1; off < 8; off <<= 1) {
            int y = __shfl_up_sync(0x000000ffu, s, off);
            if (lane >= off) s += y;
        }
        ws[lane] = s;
    }
    __syncthreads();
    int excl = (x - t) + (warp ? ws[warp - 1] : 0) + blocksums[blockIdx.x];
    if (base < N_NODES) {
        int4 rp;
        rp.x = excl;
        rp.y = excl + v.x;
        rp.z = rp.y + v.y;
        rp.w = rp.z + v.z;
        *(int4*)(rowptr + base) = rp;
        *(int4*)(cursor + base) = rp;
    }
}

__global__ void fill_kernel(const int* __restrict__ esrc, const int* __restrict__ edst,
                            int* cursor, int* srcsorted) {
    int e = blockIdx.x * blockDim.x + threadIdx.x;
    if (e < E_EDGES) {
        int pos = atomicAdd(&cursor[edst[e]], 1);
        srcsorted[pos] = esrc[e];
    }
}

// ---------------- weight prep: transpose + bf16 hi/lo split ----------------
__global__ void wprep_kernel(const float* __restrict__ W1, const float* __restrict__ W2,
                             __nv_bfloat16* __restrict__ whi, __nv_bfloat16* __restrict__ wlo) {
    int m = blockIdx.x;
    int kb = blockIdx.y;
    int n = threadIdx.x;
    const float* W = (m < 4) ? (W1 + (size_t)m * DD * DD) : (W2 + (size_t)(m - 4) * DD * DD);
    for (int k = kb * 16; k < kb * 16 + 16; k++) {
        float w = W[(size_t)k * DD + n];
        __nv_bfloat16 h16 = __float2bfloat16(w);
        float hif = __bfloat162float(h16);
        size_t o = ((size_t)m * DD + n) * DD + k;
        whi[o] = h16;
        wlo[o] = __float2bfloat16(w - hif);
    }
}

// ---------------- SpMM + eps (fp32 out) ----------------
__global__ void spmm_kernel(const float* __restrict__ h, const int* __restrict__ rowptr,
                            const int* __restrict__ srcs, const float* __restrict__ eps,
                            int l, float* __restrict__ out) {
    int node = blockIdx.x;
    int tid = threadIdx.x;  // 128
    float scale = 1.0f + __ldg(eps + l);
    float acc = scale * __ldg(h + (size_t)node * DD + tid);
    int s = __ldg(rowptr + node), e = __ldg(rowptr + node + 1);
    int i = s;
    for (; i + 3 < e; i += 4) {
        int s0 = __ldg(srcs + i + 0);
        int s1 = __ldg(srcs + i + 1);
        int s2 = __ldg(srcs + i + 2);
        int s3 = __ldg(srcs + i + 3);
        acc += __ldg(h + (size_t)s0 * DD + tid) + __ldg(h + (size_t)s1 * DD + tid)
             + __ldg(h + (size_t)s2 * DD + tid) + __ldg(h + (size_t)s3 * DD + tid);
    }
    for (; i < e; i++) acc += __ldg(h + (size_t)__ldg(srcs + i) * DD + tid);
    out[(size_t)node * DD + tid] = acc;
}

// ---------------- HMMA GEMM: C[M,128] = op(A)[M,128] @ W[128,128] + bias ----------------
// A fp32 row-major. op(A) = A when stats_in==null, else relu(BN(A)) with BN params
// computed inline from stats_in/gam/bet. Split to bf16 hi/lo while staging smem.
// D = Ahi@Whi + Ahi@Wlo + Alo@Whi. Epilogue: +bias, fp32 store, fused col stats.
#define KC 64
#define SM_AH 0
#define SM_AL 16384
#define SM_WH 32768
#define SM_WL 49152
#define SM_TOTAL 65536

__global__ __launch_bounds__(256, 2) void mma_gemm_kernel(
    const float* __restrict__ A,
    const float* __restrict__ stats_in, const float* __restrict__ gam,
    const float* __restrict__ bet,
    const __nv_bfloat16* __restrict__ Whi, const __nv_bfloat16* __restrict__ Wlo,
    const float* __restrict__ bias, float* __restrict__ Cout,
    float* __restrict__ stats_out) {
    extern __shared__ char smem[];
    __shared__ float scs[2 * DD];   // [0:128) scale, [128:256) shift
    uint32_t sb = smem_u32(smem);
    int tid = threadIdx.x, wid = tid >> 5, lane = tid & 31;
    int wm = wid >> 2, wn = wid & 3;
    int row0 = blockIdx.x * 128;
    bool apply_bn = (stats_in != nullptr);

    if (apply_bn && tid < DD) {
        const float invN = 1.0f / (float)N_NODES;
        float mean = __ldg(stats_in + tid) * invN;
        float var = __ldg(stats_in + DD + tid) * invN - mean * mean;
        float sc = __ldg(gam + tid) * rsqrtf(var + BN_EPS);
        scs[tid] = sc;
        scs[DD + tid] = __ldg(bet + tid) - sc * mean;
    }
    __syncthreads();

    float acc[4][4][4];
    #pragma unroll
    for (int i = 0; i < 4; i++)
        #pragma unroll
        for (int j = 0; j < 4; j++)
            #pragma unroll
            for (int k = 0; k < 4; k++) acc[i][j][k] = 0.f;

    int frow = ((lane >> 3) & 1) * 8 + (lane & 7);
    int fc8base = (lane >> 4);  // 0 or 1

    for (int kc = 0; kc < DD; kc += KC) {
        #pragma unroll
        for (int it = 0; it < 4; it++) {
            int idx = it * 256 + tid;      // 0..1023
            int row = idx >> 3, c8 = idx & 7;
            uint32_t d = sw(row, c8);
            int gr = row0 + row;
            int col = kc + c8 * 8;
            float4 va = make_float4(0.f, 0.f, 0.f, 0.f), vb = va;
            if (gr < N_NODES) {
                va = *(const float4*)(A + (size_t)gr * DD + col);
                vb = *(const float4*)(A + (size_t)gr * DD + col + 4);
            }
            if (apply_bn) {
                float4 s0 = *(const float4*)(scs + col);
                float4 s1 = *(const float4*)(scs + col + 4);
                float4 t0 = *(const float4*)(scs + DD + col);
                float4 t1 = *(const float4*)(scs + DD + col + 4);
                va.x = fmaxf(0.f, fmaf(s0.x, va.x, t0.x));
                va.y = fmaxf(0.f, fmaf(s0.y, va.y, t0.y));
                va.z = fmaxf(0.f, fmaf(s0.z, va.z, t0.z));
                va.w = fmaxf(0.f, fmaf(s0.w, va.w, t0.w));
                vb.x = fmaxf(0.f, fmaf(s1.x, vb.x, t1.x));
                vb.y = fmaxf(0.f, fmaf(s1.y, vb.y, t1.y));
                vb.z = fmaxf(0.f, fmaf(s1.z, vb.z, t1.z));
                vb.w = fmaxf(0.f, fmaf(s1.w, vb.w, t1.w));
            }
            uint4 hi, lo;
            split2(va.x, va.y, hi.x, lo.x);
            split2(va.z, va.w, hi.y, lo.y);
            split2(vb.x, vb.y, hi.z, lo.z);
            split2(vb.z, vb.w, hi.w, lo.w);
            *(uint4*)(smem + SM_AH + d) = hi;
            *(uint4*)(smem + SM_AL + d) = lo;
            uint4 wh = *(const uint4*)(Whi + (size_t)row * DD + col);
            uint4 wl = *(const uint4*)(Wlo + (size_t)row * DD + col);
            *(uint4*)(smem + SM_WH + d) = wh;
            *(uint4*)(smem + SM_WL + d) = wl;
        }
        __syncthreads();

        #pragma unroll
        for (int ks = 0; ks < KC / 16; ks++) {
            int c8 = ks * 2 + fc8base;
            uint32_t bh[4][2], bl[4][2];
            #pragma unroll
            for (int np = 0; np < 2; np++) {
                int n = wn * 32 + np * 16 + frow;
                uint32_t t[4];
                ldm4(t, sb + SM_WH + sw(n, c8));
                bh[np * 2 + 0][0] = t[0]; bh[np * 2 + 1][0] = t[1];
                bh[np * 2 + 0][1] = t[2]; bh[np * 2 + 1][1] = t[3];
                ldm4(t, sb + SM_WL + sw(n, c8));
                bl[np * 2 + 0][0] = t[0]; bl[np * 2 + 1][0] = t[1];
                bl[np * 2 + 0][1] = t[2]; bl[np * 2 + 1][1] = t[3];
            }
            #pragma unroll
            for (int mt = 0; mt < 4; mt++) {
                int r = wm * 64 + mt * 16 + frow;
                uint32_t ah[4], al[4];
                ldm4(ah, sb + SM_AH + sw(r, c8));
                ldm4(al, sb + SM_AL + sw(r, c8));
                #pragma unroll
                for (int nt = 0; nt < 4; nt++) {
                    mma16816(acc[mt][nt], ah, bh[nt]);
                    mma16816(acc[mt][nt], ah, bl[nt]);
                    mma16816(acc[mt][nt], al, bh[nt]);
                }
            }
        }
        __syncthreads();
    }

    // ---- epilogue: bias, store, fused column stats ----
    float st[4][4];
    #pragma unroll
    for (int nt = 0; nt < 4; nt++)
        #pragma unroll
        for (int k = 0; k < 4; k++) st[nt][k] = 0.f;

    #pragma unroll
    for (int nt = 0; nt < 4; nt++) {
        int col = wn * 32 + nt * 8 + (lane & 3) * 2;
        float2 bs = *(const float2*)(bias + col);
        #pragma unroll
        for (int mt = 0; mt < 4; mt++) {
            int r0g = row0 + wm * 64 + mt * 16 + (lane >> 2);
            float v0 = acc[mt][nt][0] + bs.x;
            float v1 = acc[mt][nt][1] + bs.y;
            float v2 = acc[mt][nt][2] + bs.x;
            float v3 = acc[mt][nt][3] + bs.y;
            if (r0g < N_NODES) {
                *(float2*)(Cout + (size_t)r0g * DD + col) = make_float2(v0, v1);
                st[nt][0] += v0; st[nt][1] += v1;
                st[nt][2] = fmaf(v0, v0, st[nt][2]);
                st[nt][3] = fmaf(v1, v1, st[nt][3]);
            }
            if (r0g + 8 < N_NODES) {
                *(float2*)(Cout + (size_t)(r0g + 8) * DD + col) = make_float2(v2, v3);
                st[nt][0] += v2; st[nt][1] += v3;
                st[nt][2] = fmaf(v2, v2, st[nt][2]);
                st[nt][3] = fmaf(v3, v3, st[nt][3]);
            }
        }
    }
    #pragma unroll
    for (int nt = 0; nt < 4; nt++) {
        #pragma unroll
        for (int off = 4; off < 32; off <<= 1) {
            #pragma unroll
            for (int k = 0; k < 4; k++)
                st[nt][k] += __shfl_xor_sync(0xffffffffu, st[nt][k], off);
        }
    }
    if (lane < 4) {
        #pragma unroll
        for (int nt = 0; nt < 4; nt++) {
            int col = wn * 32 + nt * 8 + lane * 2;
            atomicAdd(stats_out + col,          st[nt][0]);
            atomicAdd(stats_out + col + 1,      st[nt][1]);
            atomicAdd(stats_out + DD + col,     st[nt][2]);
            atomicAdd(stats_out + DD + col + 1, st[nt][3]);
        }
    }
}

// ---------------- BN2 (inline finalize) + ReLU + per-graph pooling ----------------
__global__ void apply_pool_kernel(const float* __restrict__ z, const float* __restrict__ stats,
                                  const float* __restrict__ g, const float* __restrict__ beta,
                                  const int* __restrict__ gid, float* __restrict__ h,
                                  float* __restrict__ gp) {
    int tid = threadIdx.x;  // 128
    int r0 = blockIdx.x * APPLY_ROWS;
    if (r0 >= N_NODES) return;
    int rend = min(r0 + APPLY_ROWS, N_NODES);
    const float invN = 1.0f / (float)N_NODES;
    float mean = __ldg(stats + tid) * invN;
    float var = __ldg(stats + DD + tid) * invN - mean * mean;
    float sc = __ldg(g + tid) * rsqrtf(var + BN_EPS);
    float sh = __ldg(beta + tid) - sc * mean;
    float acc = 0.f;
    int curg = __ldg(gid + r0);
    for (int r = r0; r < rend; r++) {
        float v = z[(size_t)r * DD + tid];
        float hv = fmaxf(0.f, fmaf(sc, v, sh));
        h[(size_t)r * DD + tid] = hv;
        int gcur = __ldg(gid + r);
        if (gcur != curg) {
            atomicAdd(gp + (size_t)curg * DD + tid, acc);
            acc = 0.f;
            curg = gcur;
        }
        acc += hv;
    }
    atomicAdd(gp + (size_t)curg * DD + tid, acc);
}

__global__ void pool_x_kernel(const float* __restrict__ x, const int* __restrict__ gid,
                              float* __restrict__ gp) {
    int tid = threadIdx.x;
    int r0 = blockIdx.x * APPLY_ROWS;
    if (r0 >= N_NODES) return;
    int rend = min(r0 + APPLY_ROWS, N_NODES);
    float acc = 0.f;
    int curg = __ldg(gid + r0);
    for (int r = r0; r < rend; r++) {
        float v = x[(size_t)r * DD + tid];
        int gcur = __ldg(gid + r);
        if (gcur != curg) {
            atomicAdd(gp + (size_t)curg * DD + tid, acc);
            acc = 0.f;
            curg = gcur;
        }
        acc += v;
    }
    atomicAdd(gp + (size_t)curg * DD + tid, acc);
}

// ---------------- readout ----------------
__global__ void readout_kernel(const float* __restrict__ gp, const float* __restrict__ Wp,
                               const float* __restrict__ bp, float* __restrict__ out) {
    int g = blockIdx.x;
    int tid = threadIdx.x;  // 128
    int lane = tid & 31, warp = tid >> 5;
    float partial[CC];
    #pragma unroll
    for (int c = 0; c < CC; c++) partial[c] = 0.f;
    for (int l = 0; l < 5; l++) {
        float v = gp[((size_t)l * GG + g) * DD + tid];
        const float* w = Wp + ((size_t)l * DD + tid) * CC;
        #pragma unroll
        for (int c = 0; c < CC; c++) partial[c] = fmaf(v, __ldg(w + c), partial[c]);
    }
    __shared__ float red[4][CC];
    #pragma unroll
    for (int c = 0; c < CC; c++) {
        float v = partial[c];
        #pragma unroll
        for (int off = 16; off; off >>= 1) v += __shfl_down_sync(0xffffffffu, v, off);
        if (lane == 0) red[warp][c] = v;
    }
    __syncthreads();
    if (tid < CC) {
        float s = red[0][tid] + red[1][tid] + red[2][tid] + red[3][tid];
        float b = 0.f;
        #pragma unroll
        for (int l = 0; l < 5; l++) b += __ldg(bp + l * CC + tid);
        out[g * CC + tid] = s + b;
    }
}

// ---------------- host orchestration ----------------
extern "C" void kernel_launch(void* const* d_in, const int* in_sizes, int n_in,
                              void* d_out, int out_size) {
    const float* x     = (const float*)d_in[0];
    const float* eps   = (const float*)d_in[1];
    const float* W1    = (const float*)d_in[2];
    const float* b1    = (const float*)d_in[3];
    const float* g1    = (const float*)d_in[4];
    const float* beta1 = (const float*)d_in[5];
    const float* W2    = (const float*)d_in[6];
    const float* b2    = (const float*)d_in[7];
    const float* g2    = (const float*)d_in[8];
    const float* beta2 = (const float*)d_in[9];
    const float* Wp    = (const float*)d_in[10];
    const float* bp    = (const float*)d_in[11];
    const int* esrc    = (const int*)d_in[12];
    const int* edst    = (const int*)d_in[13];
    const int* gid     = (const int*)d_in[14];
    float* out = (float*)d_out;

    float *hbuf, *pooled, *z1, *z2, *gp, *stats;
    __nv_bfloat16 *whi, *wlo;
    int *counts, *rowptr, *cursor, *srcsorted, *blocksums;
    cudaGetSymbolAddress((void**)&hbuf, g_h);
    cudaGetSymbolAddress((void**)&pooled, g_pooled);
    cudaGetSymbolAddress((void**)&z1, g_z1);
    cudaGetSymbolAddress((void**)&z2, g_z2);
    cudaGetSymbolAddress((void**)&whi, g_whi);
    cudaGetSymbolAddress((void**)&wlo, g_wlo);
    cudaGetSymbolAddress((void**)&gp, g_gp);
    cudaGetSymbolAddress((void**)&stats, g_stats);
    cudaGetSymbolAddress((void**)&counts, g_counts);
    cudaGetSymbolAddress((void**)&rowptr, g_rowptr);
    cudaGetSymbolAddress((void**)&cursor, g_cursor);
    cudaGetSymbolAddress((void**)&srcsorted, g_srcsorted);
    cudaGetSymbolAddress((void**)&blocksums, g_blocksums);

    cudaFuncSetAttribute(mma_gemm_kernel, cudaFuncAttributeMaxDynamicSharedMemorySize, SM_TOTAL);

    zero_kernel<<<256, 256>>>(gp, 5 * GG * DD, stats, NLAYERS * 2 * 2 * DD, counts, N_NODES);
    wprep_kernel<<<dim3(8, 8), 128>>>(W1, W2, whi, wlo);
    count_kernel<<<(E_EDGES + 255) / 256, 256>>>(edst, counts);
    scan_pass1<<<SCAN_BLOCKS, 256>>>(counts, blocksums);
    scan_pass2<<<1, 1>>>(blocksums, rowptr);
    scan_pass3<<<SCAN_BLOCKS, 256>>>(counts, blocksums, rowptr, cursor);
    fill_kernel<<<(E_EDGES + 255) / 256, 256>>>(esrc, edst, cursor, srcsorted);
    pool_x_kernel<<<(N_NODES + APPLY_ROWS - 1) / APPLY_ROWS, 128>>>(x, gid, gp);

    const float* h = x;
    for (int l = 0; l < NLAYERS; l++) {
        float* st1 = stats + (l * 2 + 0) * 2 * DD;
        float* st2 = stats + (l * 2 + 1) * 2 * DD;

        spmm_kernel<<<N_NODES, 128>>>(h, rowptr, srcsorted, eps, l, pooled);
        mma_gemm_kernel<<<MTILES, 256, SM_TOTAL>>>(
            pooled, nullptr, nullptr, nullptr,
            whi + (size_t)l * DD * DD, wlo + (size_t)l * DD * DD,
            b1 + l * DD, z1, st1);
        mma_gemm_kernel<<<MTILES, 256, SM_TOTAL>>>(
            z1, st1, g1 + l * DD, beta1 + l * DD,
            whi + (size_t)(4 + l) * DD * DD, wlo + (size_t)(4 + l) * DD * DD,
            b2 + l * DD, z2, st2);
        apply_pool_kernel<<<(N_NODES + APPLY_ROWS - 1) / APPLY_ROWS, 128>>>(
            z2, st2, g2 + l * DD, beta2 + l * DD, gid, hbuf, gp + (size_t)(l + 1) * GG * DD);
        h = hbuf;
    }
    readout_kernel<<<GG, 128>>>(gp, Wp, bp, out);
}

// round 6
// speedup vs baseline: 1.8785x; 1.1560x over previous
#include <cuda_runtime.h>
#include <cuda_bf16.h>
#include <cstdint>

#define N_NODES 50000
#define E_EDGES 800000
#define DD 128
#define GG 256
#define CC 16
#define NLAYERS 4   // L-1 GIN layers
#define BN_EPS 1e-5f
#define POOL_ROWS 64
#define MTILES ((N_NODES + 127) / 128)   // 391
#define SCAN_BLOCKS ((N_NODES + 1023) / 1024)  // 49
#define NODES_PER_WARP 8
#define SPMM_BLOCKS ((N_NODES + 8 * NODES_PER_WARP - 1) / (8 * NODES_PER_WARP))

// ---------------- device scratch (no allocation allowed) ----------------
__device__ float g_pooled[(size_t)N_NODES * DD]; // spmm output
__device__ float g_z1[(size_t)N_NODES * DD];     // z1 (pre-BN1)
__device__ float g_z2[(size_t)N_NODES * DD];     // z2 (pre-BN2) == layer state
__device__ __nv_bfloat16 g_whi[8 * DD * DD];     // transposed split weights [n][k]
__device__ __nv_bfloat16 g_wlo[8 * DD * DD];
__device__ float g_gp[5 * GG * DD];              // per-layer graph pools
__device__ float g_stats[NLAYERS * 2 * 2 * DD];  // sums / sumsq per (layer,bn)
__device__ int   g_counts[N_NODES];
__device__ int   g_rowptr[N_NODES + 1];
__device__ int   g_cursor[N_NODES];
__device__ int   g_srcsorted[E_EDGES];
__device__ int   g_blocksums[SCAN_BLOCKS];

// ================= warp-MMA helpers (portable, sm_80+) =================
__device__ __forceinline__ uint32_t smem_u32(const void* p) {
    uint32_t a;
    asm("{ .reg .u64 t; cvta.to.shared.u64 t, %1; cvt.u32.u64 %0, t; }" : "=r"(a) : "l"(p));
    return a;
}
__device__ __forceinline__ void ldm4(uint32_t* r, uint32_t addr) {
    asm volatile("ldmatrix.sync.aligned.m8n8.x4.shared.b16 {%0,%1,%2,%3}, [%4];"
        : "=r"(r[0]), "=r"(r[1]), "=r"(r[2]), "=r"(r[3]) : "r"(addr));
}
__device__ __forceinline__ void mma16816(float* d, const uint32_t* a, const uint32_t* b) {
    asm volatile("mma.sync.aligned.m16n8k16.row.col.f32.bf16.bf16.f32 "
        "{%0,%1,%2,%3}, {%4,%5,%6,%7}, {%8,%9}, {%0,%1,%2,%3};"
        : "+f"(d[0]), "+f"(d[1]), "+f"(d[2]), "+f"(d[3])
        : "r"(a[0]), "r"(a[1]), "r"(a[2]), "r"(a[3]), "r"(b[0]), "r"(b[1]));
}
__device__ __forceinline__ uint32_t sw(int row, int c8) {
    return (uint32_t)(row * 128 + ((c8 ^ (row & 7)) * 16));
}
__device__ __forceinline__ void split2(float a, float b, uint32_t& hi, uint32_t& lo) {
    __nv_bfloat162 h, l;
    h.x = __float2bfloat16(a); h.y = __float2bfloat16(b);
    l.x = __float2bfloat16(a - __bfloat162float(h.x));
    l.y = __float2bfloat16(b - __bfloat162float(h.y));
    hi = *(uint32_t*)&h; lo = *(uint32_t*)&l;
}
__device__ __forceinline__ float4 bnrelu4(float4 v, float4 sc, float4 sh) {
    v.x = fmaxf(0.f, fmaf(sc.x, v.x, sh.x));
    v.y = fmaxf(0.f, fmaf(sc.y, v.y, sh.y));
    v.z = fmaxf(0.f, fmaf(sc.z, v.z, sh.z));
    v.w = fmaxf(0.f, fmaf(sc.w, v.w, sh.w));
    return v;
}

// ---------------- utility: zero scratch ----------------
__global__ void zero_kernel(float* a, int na, float* b, int nb, int* c, int nc) {
    int i = blockIdx.x * blockDim.x + threadIdx.x;
    int stride = gridDim.x * blockDim.x;
    for (int j = i; j < na; j += stride) a[j] = 0.f;
    for (int j = i; j < nb; j += stride) b[j] = 0.f;
    for (int j = i; j < nc; j += stride) c[j] = 0;
}

// ---------------- CSR build ----------------
__global__ void count_kernel(const int* __restrict__ edst, int* counts) {
    int e = blockIdx.x * blockDim.x + threadIdx.x;
    if (e < E_EDGES) atomicAdd(&counts[edst[e]], 1);
}

__global__ void scan_pass1(const int* __restrict__ counts, int* __restrict__ blocksums) {
    __shared__ int ws[8];
    int tid = threadIdx.x, lane = tid & 31, warp = tid >> 5;
    int base = blockIdx.x * 1024 + tid * 4;
    int4 v = make_int4(0, 0, 0, 0);
    if (base < N_NODES) v = *(const int4*)(counts + base);
    int s = v.x + v.y + v.z + v.w;
    #pragma unroll
    for (int off = 16; off; off >>= 1) s += __shfl_xor_sync(0xffffffffu, s, off);
    if (lane == 0) ws[warp] = s;
    __syncthreads();
    if (tid == 0) {
        int t = 0;
        #pragma unroll
        for (int w = 0; w < 8; w++) t += ws[w];
        blocksums[blockIdx.x] = t;
    }
}

__global__ void scan_pass2(int* __restrict__ blocksums, int* __restrict__ rowptr) {
    int run = 0;
    for (int i = 0; i < SCAN_BLOCKS; i++) {
        int v = blocksums[i];
        blocksums[i] = run;
        run += v;
    }
    rowptr[N_NODES] = run;
}

__global__ void scan_pass3(const int* __restrict__ counts, const int* __restrict__ blocksums,
                           int* __restrict__ rowptr, int* __restrict__ cursor) {
    __shared__ int ws[8];
    int tid = threadIdx.x, lane = tid & 31, warp = tid >> 5;
    int base = blockIdx.x * 1024 + tid * 4;
    int4 v = make_int4(0, 0, 0, 0);
    if (base < N_NODES) v = *(const int4*)(counts + base);
    int t = v.x + v.y + v.z + v.w;
    int x = t;
    #pragma unroll
    for (int off = 1; off < 32; off <<= 1) {
        int y = __shfl_up_sync(0xffffffffu, x, off);
        if (lane >= off) x += y;
    }
    if (lane == 31) ws[warp] = x;
    __syncthreads();
    if (warp == 0 && lane < 8) {
        int s = ws[lane];
        #pragma unroll
        for (int off = 1; off < 8; off <<= 1) {
            int y = __shfl_up_sync(0x000000ffu, s, off);
            if (lane >= off) s += y;
        }
        ws[lane] = s;
    }
    __syncthreads();
    int excl = (x - t) + (warp ? ws[warp - 1] : 0) + blocksums[blockIdx.x];
    if (base < N_NODES) {
        int4 rp;
        rp.x = excl;
        rp.y = excl + v.x;
        rp.z = rp.y + v.y;
        rp.w = rp.z + v.z;
        *(int4*)(rowptr + base) = rp;
        *(int4*)(cursor + base) = rp;
    }
}

__global__ void fill_kernel(const int* __restrict__ esrc, const int* __restrict__ edst,
                            int* cursor, int* srcsorted) {
    int e = blockIdx.x * blockDim.x + threadIdx.x;
    if (e < E_EDGES) {
        int pos = atomicAdd(&cursor[edst[e]], 1);
        srcsorted[pos] = esrc[e];
    }
}

// ---------------- weight prep: transpose + bf16 hi/lo split ----------------
__global__ void wprep_kernel(const float* __restrict__ W1, const float* __restrict__ W2,
                             __nv_bfloat16* __restrict__ whi, __nv_bfloat16* __restrict__ wlo) {
    int m = blockIdx.x;
    int kb = blockIdx.y;
    int n = threadIdx.x;
    const float* W = (m < 4) ? (W1 + (size_t)m * DD * DD) : (W2 + (size_t)(m - 4) * DD * DD);
    for (int k = kb * 16; k < kb * 16 + 16; k++) {
        float w = W[(size_t)k * DD + n];
        __nv_bfloat16 h16 = __float2bfloat16(w);
        float hif = __bfloat162float(h16);
        size_t o = ((size_t)m * DD + n) * DD + k;
        whi[o] = h16;
        wlo[o] = __float2bfloat16(w - hif);
    }
}

// ---------------- fused SpMM: gather BN(feat) + eps-self + per-graph pooling ----------------
// feat = x (APPLY_BN=false) or z2 (APPLY_BN=true; BN params from stats/gam/bet).
// h_node = op(feat[node]); pooled[node] = (1+eps)*h_node + sum_{src} op(feat[src]);
// also atomicAdd per-graph sum of h_node into gp (run-length by sorted gid).
template<bool APPLY_BN>
__global__ __launch_bounds__(256) void spmm_fused_kernel(
    const float* __restrict__ feat,
    const float* __restrict__ stats, const float* __restrict__ gam,
    const float* __restrict__ bet,
    const int* __restrict__ rowptr, const int* __restrict__ srcs,
    const float* __restrict__ eps, int l, const int* __restrict__ gid,
    float* __restrict__ pooled, float* __restrict__ gp) {
    int lane = threadIdx.x & 31, warp = threadIdx.x >> 5;
    int node0 = (blockIdx.x * 8 + warp) * NODES_PER_WARP;
    if (node0 >= N_NODES) return;
    int nend = min(node0 + NODES_PER_WARP, N_NODES);
    int c = lane * 4;
    float scale = 1.0f + __ldg(eps + l);

    float4 sc, sh;
    if (APPLY_BN) {
        const float invN = 1.0f / (float)N_NODES;
        float4 sm = *(const float4*)(stats + c);
        float4 sq = *(const float4*)(stats + DD + c);
        float4 gg = *(const float4*)(gam + c);
        float4 bb = *(const float4*)(bet + c);
        float m0 = sm.x * invN, m1 = sm.y * invN, m2 = sm.z * invN, m3 = sm.w * invN;
        sc.x = gg.x * rsqrtf(sq.x * invN - m0 * m0 + BN_EPS);
        sc.y = gg.y * rsqrtf(sq.y * invN - m1 * m1 + BN_EPS);
        sc.z = gg.z * rsqrtf(sq.z * invN - m2 * m2 + BN_EPS);
        sc.w = gg.w * rsqrtf(sq.w * invN - m3 * m3 + BN_EPS);
        sh.x = bb.x - sc.x * m0; sh.y = bb.y - sc.y * m1;
        sh.z = bb.z - sc.z * m2; sh.w = bb.w - sc.w * m3;
    }

    float4 pacc = make_float4(0.f, 0.f, 0.f, 0.f);
    int curg = __ldg(gid + node0);

    for (int node = node0; node < nend; node++) {
        float4 hv = *(const float4*)(feat + (size_t)node * DD + c);
        if (APPLY_BN) hv = bnrelu4(hv, sc, sh);

        // pooling (run-length over sorted graph ids)
        int gcur = __ldg(gid + node);
        if (gcur != curg) {
            float* gpd = gp + (size_t)curg * DD + c;
            atomicAdd(gpd + 0, pacc.x); atomicAdd(gpd + 1, pacc.y);
            atomicAdd(gpd + 2, pacc.z); atomicAdd(gpd + 3, pacc.w);
            pacc = make_float4(0.f, 0.f, 0.f, 0.f);
            curg = gcur;
        }
        pacc.x += hv.x; pacc.y += hv.y; pacc.z += hv.z; pacc.w += hv.w;

        float4 acc;
        acc.x = scale * hv.x; acc.y = scale * hv.y;
        acc.z = scale * hv.z; acc.w = scale * hv.w;

        int s = __ldg(rowptr + node), e = __ldg(rowptr + node + 1);
        int i = s;
        for (; i + 3 < e; i += 4) {
            int s0 = __ldg(srcs + i + 0);
            int s1 = __ldg(srcs + i + 1);
            int s2 = __ldg(srcs + i + 2);
            int s3 = __ldg(srcs + i + 3);
            float4 v0 = *(const float4*)(feat + (size_t)s0 * DD + c);
            float4 v1 = *(const float4*)(feat + (size_t)s1 * DD + c);
            float4 v2 = *(const float4*)(feat + (size_t)s2 * DD + c);
            float4 v3 = *(const float4*)(feat + (size_t)s3 * DD + c);
            if (APPLY_BN) {
                v0 = bnrelu4(v0, sc, sh); v1 = bnrelu4(v1, sc, sh);
                v2 = bnrelu4(v2, sc, sh); v3 = bnrelu4(v3, sc, sh);
            }
            acc.x += v0.x + v1.x + v2.x + v3.x;
            acc.y += v0.y + v1.y + v2.y + v3.y;
            acc.z += v0.z + v1.z + v2.z + v3.z;
            acc.w += v0.w + v1.w + v2.w + v3.w;
        }
        for (; i < e; i++) {
            int s0 = __ldg(srcs + i);
            float4 v0 = *(const float4*)(feat + (size_t)s0 * DD + c);
            if (APPLY_BN) v0 = bnrelu4(v0, sc, sh);
            acc.x += v0.x; acc.y += v0.y; acc.z += v0.z; acc.w += v0.w;
        }
        *(float4*)(pooled + (size_t)node * DD + c) = acc;
    }
    float* gpd = gp + (size_t)curg * DD + c;
    atomicAdd(gpd + 0, pacc.x); atomicAdd(gpd + 1, pacc.y);
    atomicAdd(gpd + 2, pacc.z); atomicAdd(gpd + 3, pacc.w);
}

// ---------------- HMMA GEMM: C[M,128] = op(A)[M,128] @ W[128,128] + bias ----------------
#define KC 64
#define SM_AH 0
#define SM_AL 16384
#define SM_WH 32768
#define SM_WL 49152
#define SM_TOTAL 65536

__global__ __launch_bounds__(256, 2) void mma_gemm_kernel(
    const float* __restrict__ A,
    const float* __restrict__ stats_in, const float* __restrict__ gam,
    const float* __restrict__ bet,
    const __nv_bfloat16* __restrict__ Whi, const __nv_bfloat16* __restrict__ Wlo,
    const float* __restrict__ bias, float* __restrict__ Cout,
    float* __restrict__ stats_out) {
    extern __shared__ char smem[];
    __shared__ float scs[2 * DD];
    uint32_t sb = smem_u32(smem);
    int tid = threadIdx.x, wid = tid >> 5, lane = tid & 31;
    int wm = wid >> 2, wn = wid & 3;
    int row0 = blockIdx.x * 128;
    bool apply_bn = (stats_in != nullptr);

    if (apply_bn && tid < DD) {
        const float invN = 1.0f / (float)N_NODES;
        float mean = __ldg(stats_in + tid) * invN;
        float var = __ldg(stats_in + DD + tid) * invN - mean * mean;
        float sc = __ldg(gam + tid) * rsqrtf(var + BN_EPS);
        scs[tid] = sc;
        scs[DD + tid] = __ldg(bet + tid) - sc * mean;
    }
    __syncthreads();

    float acc[4][4][4];
    #pragma unroll
    for (int i = 0; i < 4; i++)
        #pragma unroll
        for (int j = 0; j < 4; j++)
            #pragma unroll
            for (int k = 0; k < 4; k++) acc[i][j][k] = 0.f;

    int frow = ((lane >> 3) & 1) * 8 + (lane & 7);
    int fc8base = (lane >> 4);

    for (int kc = 0; kc < DD; kc += KC) {
        #pragma unroll
        for (int it = 0; it < 4; it++) {
            int idx = it * 256 + tid;
            int row = idx >> 3, c8 = idx & 7;
            uint32_t d = sw(row, c8);
            int gr = row0 + row;
            int col = kc + c8 * 8;
            float4 va = make_float4(0.f, 0.f, 0.f, 0.f), vb = va;
            if (gr < N_NODES) {
                va = *(const float4*)(A + (size_t)gr * DD + col);
                vb = *(const float4*)(A + (size_t)gr * DD + col + 4);
            }
            if (apply_bn) {
                float4 s0 = *(const float4*)(scs + col);
                float4 s1 = *(const float4*)(scs + col + 4);
                float4 t0 = *(const float4*)(scs + DD + col);
                float4 t1 = *(const float4*)(scs + DD + col + 4);
                va = bnrelu4(va, s0, t0);
                vb = bnrelu4(vb, s1, t1);
            }
            uint4 hi, lo;
            split2(va.x, va.y, hi.x, lo.x);
            split2(va.z, va.w, hi.y, lo.y);
            split2(vb.x, vb.y, hi.z, lo.z);
            split2(vb.z, vb.w, hi.w, lo.w);
            *(uint4*)(smem + SM_AH + d) = hi;
            *(uint4*)(smem + SM_AL + d) = lo;
            uint4 wh = *(const uint4*)(Whi + (size_t)row * DD + col);
            uint4 wl = *(const uint4*)(Wlo + (size_t)row * DD + col);
            *(uint4*)(smem + SM_WH + d) = wh;
            *(uint4*)(smem + SM_WL + d) = wl;
        }
        __syncthreads();

        #pragma unroll
        for (int ks = 0; ks < KC / 16; ks++) {
            int c8 = ks * 2 + fc8base;
            uint32_t bh[4][2], bl[4][2];
            #pragma unroll
            for (int np = 0; np < 2; np++) {
                int n = wn * 32 + np * 16 + frow;
                uint32_t t[4];
                ldm4(t, sb + SM_WH + sw(n, c8));
                bh[np * 2 + 0][0] = t[0]; bh[np * 2 + 1][0] = t[1];
                bh[np * 2 + 0][1] = t[2]; bh[np * 2 + 1][1] = t[3];
                ldm4(t, sb + SM_WL + sw(n, c8));
                bl[np * 2 + 0][0] = t[0]; bl[np * 2 + 1][0] = t[1];
                bl[np * 2 + 0][1] = t[2]; bl[np * 2 + 1][1] = t[3];
            }
            #pragma unroll
            for (int mt = 0; mt < 4; mt++) {
                int r = wm * 64 + mt * 16 + frow;
                uint32_t ah[4], al[4];
                ldm4(ah, sb + SM_AH + sw(r, c8));
                ldm4(al, sb + SM_AL + sw(r, c8));
                #pragma unroll
                for (int nt = 0; nt < 4; nt++) {
                    mma16816(acc[mt][nt], ah, bh[nt]);
                    mma16816(acc[mt][nt], ah, bl[nt]);
                    mma16816(acc[mt][nt], al, bh[nt]);
                }
            }
        }
        __syncthreads();
    }

    float st[4][4];
    #pragma unroll
    for (int nt = 0; nt < 4; nt++)
        #pragma unroll
        for (int k = 0; k < 4; k++) st[nt][k] = 0.f;

    #pragma unroll
    for (int nt = 0; nt < 4; nt++) {
        int col = wn * 32 + nt * 8 + (lane & 3) * 2;
        float2 bs = *(const float2*)(bias + col);
        #pragma unroll
        for (int mt = 0; mt < 4; mt++) {
            int r0g = row0 + wm * 64 + mt * 16 + (lane >> 2);
            float v0 = acc[mt][nt][0] + bs.x;
            float v1 = acc[mt][nt][1] + bs.y;
            float v2 = acc[mt][nt][2] + bs.x;
            float v3 = acc[mt][nt][3] + bs.y;
            if (r0g < N_NODES) {
                *(float2*)(Cout + (size_t)r0g * DD + col) = make_float2(v0, v1);
                st[nt][0] += v0; st[nt][1] += v1;
                st[nt][2] = fmaf(v0, v0, st[nt][2]);
                st[nt][3] = fmaf(v1, v1, st[nt][3]);
            }
            if (r0g + 8 < N_NODES) {
                *(float2*)(Cout + (size_t)(r0g + 8) * DD + col) = make_float2(v2, v3);
                st[nt][0] += v2; st[nt][1] += v3;
                st[nt][2] = fmaf(v2, v2, st[nt][2]);
                st[nt][3] = fmaf(v3, v3, st[nt][3]);
            }
        }
    }
    #pragma unroll
    for (int nt = 0; nt < 4; nt++) {
        #pragma unroll
        for (int off = 4; off < 32; off <<= 1) {
            #pragma unroll
            for (int k = 0; k < 4; k++)
                st[nt][k] += __shfl_xor_sync(0xffffffffu, st[nt][k], off);
        }
    }
    if (lane < 4) {
        #pragma unroll
        for (int nt = 0; nt < 4; nt++) {
            int col = wn * 32 + nt * 8 + lane * 2;
            atomicAdd(stats_out + col,          st[nt][0]);
            atomicAdd(stats_out + col + 1,      st[nt][1]);
            atomicAdd(stats_out + DD + col,     st[nt][2]);
            atomicAdd(stats_out + DD + col + 1, st[nt][3]);
        }
    }
}

// ---------------- final pool: BN2(z2)+ReLU summed per graph (no h write) ----------------
__global__ void pool_final_kernel(const float* __restrict__ z, const float* __restrict__ stats,
                                  const float* __restrict__ g, const float* __restrict__ beta,
                                  const int* __restrict__ gid, float* __restrict__ gp) {
    int tid = threadIdx.x;  // 128
    int r0 = blockIdx.x * POOL_ROWS;
    if (r0 >= N_NODES) return;
    int rend = min(r0 + POOL_ROWS, N_NODES);
    const float invN = 1.0f / (float)N_NODES;
    float mean = __ldg(stats + tid) * invN;
    float var = __ldg(stats + DD + tid) * invN - mean * mean;
    float sc = __ldg(g + tid) * rsqrtf(var + BN_EPS);
    float sh = __ldg(beta + tid) - sc * mean;
    float acc = 0.f;
    int curg = __ldg(gid + r0);
    for (int r = r0; r < rend; r++) {
        float v = z[(size_t)r * DD + tid];
        float hv = fmaxf(0.f, fmaf(sc, v, sh));
        int gcur = __ldg(gid + r);
        if (gcur != curg) {
            atomicAdd(gp + (size_t)curg * DD + tid, acc);
            acc = 0.f;
            curg = gcur;
        }
        acc += hv;
    }
    atomicAdd(gp + (size_t)curg * DD + tid, acc);
}

// ---------------- readout ----------------
__global__ void readout_kernel(const float* __restrict__ gp, const float* __restrict__ Wp,
                               const float* __restrict__ bp, float* __restrict__ out) {
    int g = blockIdx.x;
    int tid = threadIdx.x;  // 128
    int lane = tid & 31, warp = tid >> 5;
    float partial[CC];
    #pragma unroll
    for (int c = 0; c < CC; c++) partial[c] = 0.f;
    for (int l = 0; l < 5; l++) {
        float v = gp[((size_t)l * GG + g) * DD + tid];
        const float* w = Wp + ((size_t)l * DD + tid) * CC;
        #pragma unroll
        for (int c = 0; c < CC; c++) partial[c] = fmaf(v, __ldg(w + c), partial[c]);
    }
    __shared__ float red[4][CC];
    #pragma unroll
    for (int c = 0; c < CC; c++) {
        float v = partial[c];
        #pragma unroll
        for (int off = 16; off; off >>= 1) v += __shfl_down_sync(0xffffffffu, v, off);
        if (lane == 0) red[warp][c] = v;
    }
    __syncthreads();
    if (tid < CC) {
        float s = red[0][tid] + red[1][tid] + red[2][tid] + red[3][tid];
        float b = 0.f;
        #pragma unroll
        for (int l = 0; l < 5; l++) b += __ldg(bp + l * CC + tid);
        out[g * CC + tid] = s + b;
    }
}

// ---------------- host orchestration ----------------
extern "C" void kernel_launch(void* const* d_in, const int* in_sizes, int n_in,
                              void* d_out, int out_size) {
    const float* x     = (const float*)d_in[0];
    const float* eps   = (const float*)d_in[1];
    const float* W1    = (const float*)d_in[2];
    const float* b1    = (const float*)d_in[3];
    const float* g1    = (const float*)d_in[4];
    const float* beta1 = (const float*)d_in[5];
    const float* W2    = (const float*)d_in[6];
    const float* b2    = (const float*)d_in[7];
    const float* g2    = (const float*)d_in[8];
    const float* beta2 = (const float*)d_in[9];
    const float* Wp    = (const float*)d_in[10];
    const float* bp    = (const float*)d_in[11];
    const int* esrc    = (const int*)d_in[12];
    const int* edst    = (const int*)d_in[13];
    const int* gid     = (const int*)d_in[14];
    float* out = (float*)d_out;

    float *pooled, *z1, *z2, *gp, *stats;
    __nv_bfloat16 *whi, *wlo;
    int *counts, *rowptr, *cursor, *srcsorted, *blocksums;
    cudaGetSymbolAddress((void**)&pooled, g_pooled);
    cudaGetSymbolAddress((void**)&z1, g_z1);
    cudaGetSymbolAddress((void**)&z2, g_z2);
    cudaGetSymbolAddress((void**)&whi, g_whi);
    cudaGetSymbolAddress((void**)&wlo, g_wlo);
    cudaGetSymbolAddress((void**)&gp, g_gp);
    cudaGetSymbolAddress((void**)&stats, g_stats);
    cudaGetSymbolAddress((void**)&counts, g_counts);
    cudaGetSymbolAddress((void**)&rowptr, g_rowptr);
    cudaGetSymbolAddress((void**)&cursor, g_cursor);
    cudaGetSymbolAddress((void**)&srcsorted, g_srcsorted);
    cudaGetSymbolAddress((void**)&blocksums, g_blocksums);

    cudaFuncSetAttribute(mma_gemm_kernel, cudaFuncAttributeMaxDynamicSharedMemorySize, SM_TOTAL);

    zero_kernel<<<256, 256>>>(gp, 5 * GG * DD, stats, NLAYERS * 2 * 2 * DD, counts, N_NODES);
    wprep_kernel<<<dim3(8, 8), 128>>>(W1, W2, whi, wlo);
    count_kernel<<<(E_EDGES + 255) / 256, 256>>>(edst, counts);
    scan_pass1<<<SCAN_BLOCKS, 256>>>(counts, blocksums);
    scan_pass2<<<1, 1>>>(blocksums, rowptr);
    scan_pass3<<<SCAN_BLOCKS, 256>>>(counts, blocksums, rowptr, cursor);
    fill_kernel<<<(E_EDGES + 255) / 256, 256>>>(esrc, edst, cursor, srcsorted);

    for (int l = 0; l < NLAYERS; l++) {
        float* st1 = stats + (l * 2 + 0) * 2 * DD;
        float* st2 = stats + (l * 2 + 1) * 2 * DD;

        if (l == 0) {
            spmm_fused_kernel<false><<<SPMM_BLOCKS, 256>>>(
                x, nullptr, nullptr, nullptr, rowptr, srcsorted, eps, l, gid,
                pooled, gp + (size_t)l * GG * DD);
        } else {
            float* st2p = stats + ((l - 1) * 2 + 1) * 2 * DD;
            spmm_fused_kernel<true><<<SPMM_BLOCKS, 256>>>(
                z2, st2p, g2 + (l - 1) * DD, beta2 + (l - 1) * DD,
                rowptr, srcsorted, eps, l, gid,
                pooled, gp + (size_t)l * GG * DD);
        }
        mma_gemm_kernel<<<MTILES, 256, SM_TOTAL>>>(
            pooled, nullptr, nullptr, nullptr,
            whi + (size_t)l * DD * DD, wlo + (size_t)l * DD * DD,
            b1 + l * DD, z1, st1);
        mma_gemm_kernel<<<MTILES, 256, SM_TOTAL>>>(
            z1, st1, g1 + l * DD, beta1 + l * DD,
            whi + (size_t)(4 + l) * DD * DD, wlo + (size_t)(4 + l) * DD * DD,
            b2 + l * DD, z2, st2);
    }
    pool_final_kernel<<<(N_NODES + POOL_ROWS - 1) / POOL_ROWS, 128>>>(
        z2, stats + ((NLAYERS - 1) * 2 + 1) * 2 * DD,
        g2 + (NLAYERS - 1) * DD, beta2 + (NLAYERS - 1) * DD, gid,
        gp + (size_t)NLAYERS * GG * DD);
    readout_kernel<<<GG, 128>>>(gp, Wp, bp, out);
}

// round 8
// speedup vs baseline: 2.1267x; 1.1321x over previous
#include <cuda_runtime.h>
#include <cuda_bf16.h>
#include <cstdint>

#define N_NODES 50000
#define E_EDGES 800000
#define DD 128
#define GG 256
#define CC 16
#define NLAYERS 4   // L-1 GIN layers
#define BN_EPS 1e-5f
#define POOL_ROWS 64
#define MTILES ((N_NODES + 127) / 128)   // 391
#define SCAN_BLOCKS ((N_NODES + 1023) / 1024)  // 49
#define NODES_PER_WARP 8
#define SPMM_BLOCKS ((N_NODES + 8 * NODES_PER_WARP - 1) / (8 * NODES_PER_WARP))

// ---------------- device scratch (no allocation allowed) ----------------
__device__ float g_pooled[(size_t)N_NODES * DD]; // spmm output
__device__ float g_z1[(size_t)N_NODES * DD];     // z1 (pre-BN1)
__device__ float g_z2[(size_t)N_NODES * DD];     // z2 (pre-BN2) == layer state
__device__ __nv_bfloat16 g_whi[8 * DD * DD];     // transposed split weights [n][k]
__device__ __nv_bfloat16 g_wlo[8 * DD * DD];
__device__ float g_gp[5 * GG * DD];              // per-layer graph pools
__device__ float g_stats[NLAYERS * 2 * 2 * DD];  // sums / sumsq per (layer,bn)
__device__ int   g_counts[N_NODES];
__device__ int   g_rowptr[N_NODES + 1];
__device__ int   g_cursor[N_NODES];
__device__ int   g_srcsorted[E_EDGES];
__device__ int   g_blocksums[SCAN_BLOCKS];

// ================= warp-MMA helpers (portable, sm_80+) =================
__device__ __forceinline__ uint32_t smem_u32(const void* p) {
    uint32_t a;
    asm("{ .reg .u64 t; cvta.to.shared.u64 t, %1; cvt.u32.u64 %0, t; }" : "=r"(a) : "l"(p));
    return a;
}
__device__ __forceinline__ void ldm4(uint32_t* r, uint32_t addr) {
    asm volatile("ldmatrix.sync.aligned.m8n8.x4.shared.b16 {%0,%1,%2,%3}, [%4];"
        : "=r"(r[0]), "=r"(r[1]), "=r"(r[2]), "=r"(r[3]) : "r"(addr));
}
__device__ __forceinline__ void mma16816(float* d, const uint32_t* a, const uint32_t* b) {
    asm volatile("mma.sync.aligned.m16n8k16.row.col.f32.bf16.bf16.f32 "
        "{%0,%1,%2,%3}, {%4,%5,%6,%7}, {%8,%9}, {%0,%1,%2,%3};"
        : "+f"(d[0]), "+f"(d[1]), "+f"(d[2]), "+f"(d[3])
        : "r"(a[0]), "r"(a[1]), "r"(a[2]), "r"(a[3]), "r"(b[0]), "r"(b[1]));
}
__device__ __forceinline__ uint32_t sw(int row, int c8) {
    return (uint32_t)(row * 128 + ((c8 ^ (row & 7)) * 16));
}
// packed error-compensated split: {a,b} -> bf16x2 hi, bf16x2 lo
__device__ __forceinline__ void split2(float a, float b, uint32_t& hi, uint32_t& lo) {
    uint32_t h;
    asm("cvt.rn.bf16x2.f32 %0, %1, %2;" : "=r"(h) : "f"(b), "f"(a));
    float ar = a - __uint_as_float(h << 16);
    float br = b - __uint_as_float(h & 0xffff0000u);
    asm("cvt.rn.bf16x2.f32 %0, %1, %2;" : "=r"(lo) : "f"(br), "f"(ar));
    hi = h;
}
__device__ __forceinline__ void cp16(uint32_t dst, const void* src) {
    asm volatile("cp.async.cg.shared.global [%0], [%1], 16;" :: "r"(dst), "l"(src));
}
__device__ __forceinline__ float4 bnrelu4(float4 v, float4 sc, float4 sh) {
    v.x = fmaxf(0.f, fmaf(sc.x, v.x, sh.x));
    v.y = fmaxf(0.f, fmaf(sc.y, v.y, sh.y));
    v.z = fmaxf(0.f, fmaf(sc.z, v.z, sh.z));
    v.w = fmaxf(0.f, fmaf(sc.w, v.w, sh.w));
    return v;
}

// ---------------- utility: zero scratch ----------------
__global__ void zero_kernel(float* a, int na, float* b, int nb, int* c, int nc) {
    int i = blockIdx.x * blockDim.x + threadIdx.x;
    int stride = gridDim.x * blockDim.x;
    for (int j = i; j < na; j += stride) a[j] = 0.f;
    for (int j = i; j < nb; j += stride) b[j] = 0.f;
    for (int j = i; j < nc; j += stride) c[j] = 0;
}

// ---------------- CSR build ----------------
__global__ void count_kernel(const int* __restrict__ edst, int* counts) {
    int e = blockIdx.x * blockDim.x + threadIdx.x;
    if (e < E_EDGES) atomicAdd(&counts[edst[e]], 1);
}

__global__ void scan_pass1(const int* __restrict__ counts, int* __restrict__ blocksums) {
    __shared__ int ws[8];
    int tid = threadIdx.x, lane = tid & 31, warp = tid >> 5;
    int base = blockIdx.x * 1024 + tid * 4;
    int4 v = make_int4(0, 0, 0, 0);
    if (base < N_NODES) v = *(const int4*)(counts + base);
    int s = v.x + v.y + v.z + v.w;
    #pragma unroll
    for (int off = 16; off; off >>= 1) s += __shfl_xor_sync(0xffffffffu, s, off);
    if (lane == 0) ws[warp] = s;
    __syncthreads();
    if (tid == 0) {
        int t = 0;
        #pragma unroll
        for (int w = 0; w < 8; w++) t += ws[w];
        blocksums[blockIdx.x] = t;
    }
}

__global__ void scan_pass2(int* __restrict__ blocksums, int* __restrict__ rowptr) {
    int run = 0;
    for (int i = 0; i < SCAN_BLOCKS; i++) {
        int v = blocksums[i];
        blocksums[i] = run;
        run += v;
    }
    rowptr[N_NODES] = run;
}

__global__ void scan_pass3(const int* __restrict__ counts, const int* __restrict__ blocksums,
                           int* __restrict__ rowptr, int* __restrict__ cursor) {
    __shared__ int ws[8];
    int tid = threadIdx.x, lane = tid & 31, warp = tid >> 5;
    int base = blockIdx.x * 1024 + tid * 4;
    int4 v = make_int4(0, 0, 0, 0);
    if (base < N_NODES) v = *(const int4*)(counts + base);
    int t = v.x + v.y + v.z + v.w;
    int x = t;
    #pragma unroll
    for (int off = 1; off < 32; off <<= 1) {
        int y = __shfl_up_sync(0xffffffffu, x, off);
        if (lane >= off) x += y;
    }
    if (lane == 31) ws[warp] = x;
    __syncthreads();
    if (warp == 0 && lane < 8) {
        int s = ws[lane];
        #pragma unroll
        for (int off = 1; off < 8; off <<= 1) {
            int y = __shfl_up_sync(0x000000ffu, s, off);
            if (lane >= off) s += y;
        }
        ws[lane] = s;
    }
    __syncthreads();
    int excl = (x - t) + (warp ? ws[warp - 1] : 0) + blocksums[blockIdx.x];
    if (base < N_NODES) {
        int4 rp;
        rp.x = excl;
        rp.y = excl + v.x;
        rp.z = rp.y + v.y;
        rp.w = rp.z + v.z;
        *(int4*)(rowptr + base) = rp;
        *(int4*)(cursor + base) = rp;
    }
}

__global__ void fill_kernel(const int* __restrict__ esrc, const int* __restrict__ edst,
                            int* cursor, int* srcsorted) {
    int e = blockIdx.x * blockDim.x + threadIdx.x;
    if (e < E_EDGES) {
        int pos = atomicAdd(&cursor[edst[e]], 1);
        srcsorted[pos] = esrc[e];
    }
}

// ---------------- weight prep: transpose + bf16 hi/lo split ----------------
__global__ void wprep_kernel(const float* __restrict__ W1, const float* __restrict__ W2,
                             __nv_bfloat16* __restrict__ whi, __nv_bfloat16* __restrict__ wlo) {
    int m = blockIdx.x;
    int kb = blockIdx.y;
    int n = threadIdx.x;
    const float* W = (m < 4) ? (W1 + (size_t)m * DD * DD) : (W2 + (size_t)(m - 4) * DD * DD);
    for (int k = kb * 16; k < kb * 16 + 16; k++) {
        float w = W[(size_t)k * DD + n];
        __nv_bfloat16 h16 = __float2bfloat16(w);
        float hif = __bfloat162float(h16);
        size_t o = ((size_t)m * DD + n) * DD + k;
        whi[o] = h16;
        wlo[o] = __float2bfloat16(w - hif);
    }
}

// ---------------- fused SpMM: gather BN(feat) + eps-self + per-graph pooling ----------------
template<bool APPLY_BN>
__global__ __launch_bounds__(256) void spmm_fused_kernel(
    const float* __restrict__ feat,
    const float* __restrict__ stats, const float* __restrict__ gam,
    const float* __restrict__ bet,
    const int* __restrict__ rowptr, const int* __restrict__ srcs,
    const float* __restrict__ eps, int l, const int* __restrict__ gid,
    float* __restrict__ pooled, float* __restrict__ gp) {
    int lane = threadIdx.x & 31, warp = threadIdx.x >> 5;
    int node0 = (blockIdx.x * 8 + warp) * NODES_PER_WARP;
    if (node0 >= N_NODES) return;
    int nend = min(node0 + NODES_PER_WARP, N_NODES);
    int c = lane * 4;
    float scale = 1.0f + __ldg(eps + l);

    float4 sc, sh;
    if (APPLY_BN) {
        const float invN = 1.0f / (float)N_NODES;
        float4 sm = *(const float4*)(stats + c);
        float4 sq = *(const float4*)(stats + DD + c);
        float4 gg = *(const float4*)(gam + c);
        float4 bb = *(const float4*)(bet + c);
        float m0 = sm.x * invN, m1 = sm.y * invN, m2 = sm.z * invN, m3 = sm.w * invN;
        sc.x = gg.x * rsqrtf(sq.x * invN - m0 * m0 + BN_EPS);
        sc.y = gg.y * rsqrtf(sq.y * invN - m1 * m1 + BN_EPS);
        sc.z = gg.z * rsqrtf(sq.z * invN - m2 * m2 + BN_EPS);
        sc.w = gg.w * rsqrtf(sq.w * invN - m3 * m3 + BN_EPS);
        sh.x = bb.x - sc.x * m0; sh.y = bb.y - sc.y * m1;
        sh.z = bb.z - sc.z * m2; sh.w = bb.w - sc.w * m3;
    }

    float4 pacc = make_float4(0.f, 0.f, 0.f, 0.f);
    int curg = __ldg(gid + node0);

    for (int node = node0; node < nend; node++) {
        float4 hv = *(const float4*)(feat + (size_t)node * DD + c);
        if (APPLY_BN) hv = bnrelu4(hv, sc, sh);

        int gcur = __ldg(gid + node);
        if (gcur != curg) {
            float* gpd = gp + (size_t)curg * DD + c;
            atomicAdd(gpd + 0, pacc.x); atomicAdd(gpd + 1, pacc.y);
            atomicAdd(gpd + 2, pacc.z); atomicAdd(gpd + 3, pacc.w);
            pacc = make_float4(0.f, 0.f, 0.f, 0.f);
            curg = gcur;
        }
        pacc.x += hv.x; pacc.y += hv.y; pacc.z += hv.z; pacc.w += hv.w;

        float4 acc;
        acc.x = scale * hv.x; acc.y = scale * hv.y;
        acc.z = scale * hv.z; acc.w = scale * hv.w;

        int s = __ldg(rowptr + node), e = __ldg(rowptr + node + 1);
        int i = s;
        for (; i + 3 < e; i += 4) {
            int s0 = __ldg(srcs + i + 0);
            int s1 = __ldg(srcs + i + 1);
            int s2 = __ldg(srcs + i + 2);
            int s3 = __ldg(srcs + i + 3);
            float4 v0 = *(const float4*)(feat + (size_t)s0 * DD + c);
            float4 v1 = *(const float4*)(feat + (size_t)s1 * DD + c);
            float4 v2 = *(const float4*)(feat + (size_t)s2 * DD + c);
            float4 v3 = *(const float4*)(feat + (size_t)s3 * DD + c);
            if (APPLY_BN) {
                v0 = bnrelu4(v0, sc, sh); v1 = bnrelu4(v1, sc, sh);
                v2 = bnrelu4(v2, sc, sh); v3 = bnrelu4(v3, sc, sh);
            }
            acc.x += v0.x + v1.x + v2.x + v3.x;
            acc.y += v0.y + v1.y + v2.y + v3.y;
            acc.z += v0.z + v1.z + v2.z + v3.z;
            acc.w += v0.w + v1.w + v2.w + v3.w;
        }
        for (; i < e; i++) {
            int s0 = __ldg(srcs + i);
            float4 v0 = *(const float4*)(feat + (size_t)s0 * DD + c);
            if (APPLY_BN) v0 = bnrelu4(v0, sc, sh);
            acc.x += v0.x; acc.y += v0.y; acc.z += v0.z; acc.w += v0.w;
        }
        *(float4*)(pooled + (size_t)node * DD + c) = acc;
    }
    float* gpd = gp + (size_t)curg * DD + c;
    atomicAdd(gpd + 0, pacc.x); atomicAdd(gpd + 1, pacc.y);
    atomicAdd(gpd + 2, pacc.z); atomicAdd(gpd + 3, pacc.w);
}

// ---------------- HMMA GEMM: C[M,128] = op(A)[M,128] @ W[128,128] + bias ----------------
// W preloaded entirely via cp.async (4 tiles: hi/lo x chunk0/1). A fp32 loaded per
// chunk, BN-applied (optional), packed-split to bf16 hi/lo in smem.
#define SM_AH 0
#define SM_AL 16384
#define SM_W  32768                  // + (hl*2 + ch)*16384, hl-major stride 32768
#define SM_TOTAL 98304

__global__ __launch_bounds__(256, 2) void mma_gemm_kernel(
    const float* __restrict__ A,
    const float* __restrict__ stats_in, const float* __restrict__ gam,
    const float* __restrict__ bet,
    const __nv_bfloat16* __restrict__ Whi, const __nv_bfloat16* __restrict__ Wlo,
    const float* __restrict__ bias, float* __restrict__ Cout,
    float* __restrict__ stats_out) {
    extern __shared__ char smem[];
    __shared__ float scs[2 * DD];
    uint32_t sb = smem_u32(smem);
    int tid = threadIdx.x, wid = tid >> 5, lane = tid & 31;
    int wm = wid >> 2, wn = wid & 3;
    int row0 = blockIdx.x * 128;
    bool apply_bn = (stats_in != nullptr);

    // issue all W loads (global -> smem) via cp.async
    {
        const __nv_bfloat16* wsrc[2] = { Whi, Wlo };
        #pragma unroll
        for (int hl = 0; hl < 2; hl++)
            #pragma unroll
            for (int ch = 0; ch < 2; ch++)
                #pragma unroll
                for (int i = 0; i < 4; i++) {
                    int idx = i * 256 + tid;       // 0..1023
                    int row = idx >> 3, c8 = idx & 7;
                    cp16(sb + SM_W + (hl * 2 + ch) * 16384 + sw(row, c8),
                         wsrc[hl] + (size_t)row * DD + ch * 64 + c8 * 8);
                }
        asm volatile("cp.async.commit_group;" ::: "memory");
    }

    if (apply_bn && tid < DD) {
        const float invN = 1.0f / (float)N_NODES;
        float mean = __ldg(stats_in + tid) * invN;
        float var = __ldg(stats_in + DD + tid) * invN - mean * mean;
        float sc = __ldg(gam + tid) * rsqrtf(var + BN_EPS);
        scs[tid] = sc;
        scs[DD + tid] = __ldg(bet + tid) - sc * mean;
    }
    __syncthreads();   // scs visible to all threads before A staging reads it

    float acc[4][4][4];
    #pragma unroll
    for (int i = 0; i < 4; i++)
        #pragma unroll
        for (int j = 0; j < 4; j++)
            #pragma unroll
            for (int k = 0; k < 4; k++) acc[i][j][k] = 0.f;

    int frow = ((lane >> 3) & 1) * 8 + (lane & 7);
    int fc8base = (lane >> 4);

    #pragma unroll
    for (int ch = 0; ch < 2; ch++) {
        if (ch == 1) __syncthreads();   // A smem consumed by chunk-0 compute
        // load + (BN) + split A chunk into smem
        #pragma unroll
        for (int it = 0; it < 4; it++) {
            int idx = it * 256 + tid;
            int row = idx >> 3, c8 = idx & 7;
            uint32_t d = sw(row, c8);
            int gr = row0 + row;
            int col = ch * 64 + c8 * 8;
            float4 va = make_float4(0.f, 0.f, 0.f, 0.f), vb = va;
            if (gr < N_NODES) {
                va = *(const float4*)(A + (size_t)gr * DD + col);
                vb = *(const float4*)(A + (size_t)gr * DD + col + 4);
            }
            if (apply_bn) {
                float4 s0 = *(const float4*)(scs + col);
                float4 s1 = *(const float4*)(scs + col + 4);
                float4 t0 = *(const float4*)(scs + DD + col);
                float4 t1 = *(const float4*)(scs + DD + col + 4);
                va = bnrelu4(va, s0, t0);
                vb = bnrelu4(vb, s1, t1);
            }
            uint4 hi, lo;
            split2(va.x, va.y, hi.x, lo.x);
            split2(va.z, va.w, hi.y, lo.y);
            split2(vb.x, vb.y, hi.z, lo.z);
            split2(vb.z, vb.w, hi.w, lo.w);
            *(uint4*)(smem + SM_AH + d) = hi;
            *(uint4*)(smem + SM_AL + d) = lo;
        }
        if (ch == 0) asm volatile("cp.async.wait_group 0;" ::: "memory");
        __syncthreads();

        uint32_t whb = sb + SM_W + ch * 16384;           // hi tile for this chunk
        uint32_t wlb = sb + SM_W + 32768 + ch * 16384;   // lo tile for this chunk
        #pragma unroll
        for (int ks = 0; ks < 4; ks++) {
            int c8 = ks * 2 + fc8base;
            uint32_t bh[4][2], bl[4][2];
            #pragma unroll
            for (int np = 0; np < 2; np++) {
                int n = wn * 32 + np * 16 + frow;
                uint32_t t[4];
                ldm4(t, whb + sw(n, c8));
                bh[np * 2 + 0][0] = t[0]; bh[np * 2 + 1][0] = t[1];
                bh[np * 2 + 0][1] = t[2]; bh[np * 2 + 1][1] = t[3];
                ldm4(t, wlb + sw(n, c8));
                bl[np * 2 + 0][0] = t[0]; bl[np * 2 + 1][0] = t[1];
                bl[np * 2 + 0][1] = t[2]; bl[np * 2 + 1][1] = t[3];
            }
            #pragma unroll
            for (int mt = 0; mt < 4; mt++) {
                int r = wm * 64 + mt * 16 + frow;
                uint32_t ah[4], al[4];
                ldm4(ah, sb + SM_AH + sw(r, c8));
                ldm4(al, sb + SM_AL + sw(r, c8));
                #pragma unroll
                for (int nt = 0; nt < 4; nt++) {
                    mma16816(acc[mt][nt], ah, bh[nt]);
                    mma16816(acc[mt][nt], ah, bl[nt]);
                    mma16816(acc[mt][nt], al, bh[nt]);
                }
            }
        }
    }

    // ---- epilogue: bias, store, fused column stats ----
    float st[4][4];
    #pragma unroll
    for (int nt = 0; nt < 4; nt++)
        #pragma unroll
        for (int k = 0; k < 4; k++) st[nt][k] = 0.f;

    #pragma unroll
    for (int nt = 0; nt < 4; nt++) {
        int col = wn * 32 + nt * 8 + (lane & 3) * 2;
        float2 bs = *(const float2*)(bias + col);
        #pragma unroll
        for (int mt = 0; mt < 4; mt++) {
            int r0g = row0 + wm * 64 + mt * 16 + (lane >> 2);
            float v0 = acc[mt][nt][0] + bs.x;
            float v1 = acc[mt][nt][1] + bs.y;
            float v2 = acc[mt][nt][2] + bs.x;
            float v3 = acc[mt][nt][3] + bs.y;
            if (r0g < N_NODES) {
                *(float2*)(Cout + (size_t)r0g * DD + col) = make_float2(v0, v1);
                st[nt][0] += v0; st[nt][1] += v1;
                st[nt][2] = fmaf(v0, v0, st[nt][2]);
                st[nt][3] = fmaf(v1, v1, st[nt][3]);
            }
            if (r0g + 8 < N_NODES) {
                *(float2*)(Cout + (size_t)(r0g + 8) * DD + col) = make_float2(v2, v3);
                st[nt][0] += v2; st[nt][1] += v3;
                st[nt][2] = fmaf(v2, v2, st[nt][2]);
                st[nt][3] = fmaf(v3, v3, st[nt][3]);
            }
        }
    }
    #pragma unroll
    for (int nt = 0; nt < 4; nt++) {
        #pragma unroll
        for (int off = 4; off < 32; off <<= 1) {
            #pragma unroll
            for (int k = 0; k < 4; k++)
                st[nt][k] += __shfl_xor_sync(0xffffffffu, st[nt][k], off);
        }
    }
    if (lane < 4) {
        #pragma unroll
        for (int nt = 0; nt < 4; nt++) {
            int col = wn * 32 + nt * 8 + lane * 2;
            atomicAdd(stats_out + col,          st[nt][0]);
            atomicAdd(stats_out + col + 1,      st[nt][1]);
            atomicAdd(stats_out + DD + col,     st[nt][2]);
            atomicAdd(stats_out + DD + col + 1, st[nt][3]);
        }
    }
}

// ---------------- final pool: BN2(z2)+ReLU summed per graph ----------------
__global__ void pool_final_kernel(const float* __restrict__ z, const float* __restrict__ stats,
                                  const float* __restrict__ g, const float* __restrict__ beta,
                                  const int* __restrict__ gid, float* __restrict__ gp) {
    int tid = threadIdx.x;  // 128
    int r0 = blockIdx.x * POOL_ROWS;
    if (r0 >= N_NODES) return;
    int rend = min(r0 + POOL_ROWS, N_NODES);
    const float invN = 1.0f / (float)N_NODES;
    float mean = __ldg(stats + tid) * invN;
    float var = __ldg(stats + DD + tid) * invN - mean * mean;
    float sc = __ldg(g + tid) * rsqrtf(var + BN_EPS);
    float sh = __ldg(beta + tid) - sc * mean;
    float acc = 0.f;
    int curg = __ldg(gid + r0);
    for (int r = r0; r < rend; r++) {
        float v = z[(size_t)r * DD + tid];
        float hv = fmaxf(0.f, fmaf(sc, v, sh));
        int gcur = __ldg(gid + r);
        if (gcur != curg) {
            atomicAdd(gp + (size_t)curg * DD + tid, acc);
            acc = 0.f;
            curg = gcur;
        }
        acc += hv;
    }
    atomicAdd(gp + (size_t)curg * DD + tid, acc);
}

// ---------------- readout ----------------
__global__ void readout_kernel(const float* __restrict__ gp, const float* __restrict__ Wp,
                               const float* __restrict__ bp, float* __restrict__ out) {
    int g = blockIdx.x;
    int tid = threadIdx.x;  // 128
    int lane = tid & 31, warp = tid >> 5;
    float partial[CC];
    #pragma unroll
    for (int c = 0; c < CC; c++) partial[c] = 0.f;
    for (int l = 0; l < 5; l++) {
        float v = gp[((size_t)l * GG + g) * DD + tid];
        const float* w = Wp + ((size_t)l * DD + tid) * CC;
        #pragma unroll
        for (int c = 0; c < CC; c++) partial[c] = fmaf(v, __ldg(w + c), partial[c]);
    }
    __shared__ float red[4][CC];
    #pragma unroll
    for (int c = 0; c < CC; c++) {
        float v = partial[c];
        #pragma unroll
        for (int off = 16; off; off >>= 1) v += __shfl_down_sync(0xffffffffu, v, off);
        if (lane == 0) red[warp][c] = v;
    }
    __syncthreads();
    if (tid < CC) {
        float s = red[0][tid] + red[1][tid] + red[2][tid] + red[3][tid];
        float b = 0.f;
        #pragma unroll
        for (int l = 0; l < 5; l++) b += __ldg(bp + l * CC + tid);
        out[g * CC + tid] = s + b;
    }
}

// ---------------- host orchestration ----------------
extern "C" void kernel_launch(void* const* d_in, const int* in_sizes, int n_in,
                              void* d_out, int out_size) {
    const float* x     = (const float*)d_in[0];
    const float* eps   = (const float*)d_in[1];
    const float* W1    = (const float*)d_in[2];
    const float* b1    = (const float*)d_in[3];
    const float* g1    = (const float*)d_in[4];
    const float* beta1 = (const float*)d_in[5];
    const float* W2    = (const float*)d_in[6];
    const float* b2    = (const float*)d_in[7];
    const float* g2    = (const float*)d_in[8];
    const float* beta2 = (const float*)d_in[9];
    const float* Wp    = (const float*)d_in[10];
    const float* bp    = (const float*)d_in[11];
    const int* esrc    = (const int*)d_in[12];
    const int* edst    = (const int*)d_in[13];
    const int* gid     = (const int*)d_in[14];
    float* out = (float*)d_out;

    float *pooled, *z1, *z2, *gp, *stats;
    __nv_bfloat16 *whi, *wlo;
    int *counts, *rowptr, *cursor, *srcsorted, *blocksums;
    cudaGetSymbolAddress((void**)&pooled, g_pooled);
    cudaGetSymbolAddress((void**)&z1, g_z1);
    cudaGetSymbolAddress((void**)&z2, g_z2);
    cudaGetSymbolAddress((void**)&whi, g_whi);
    cudaGetSymbolAddress((void**)&wlo, g_wlo);
    cudaGetSymbolAddress((void**)&gp, g_gp);
    cudaGetSymbolAddress((void**)&stats, g_stats);
    cudaGetSymbolAddress((void**)&counts, g_counts);
    cudaGetSymbolAddress((void**)&rowptr, g_rowptr);
    cudaGetSymbolAddress((void**)&cursor, g_cursor);
    cudaGetSymbolAddress((void**)&srcsorted, g_srcsorted);
    cudaGetSymbolAddress((void**)&blocksums, g_blocksums);

    cudaFuncSetAttribute(mma_gemm_kernel, cudaFuncAttributeMaxDynamicSharedMemorySize, SM_TOTAL);

    zero_kernel<<<256, 256>>>(gp, 5 * GG * DD, stats, NLAYERS * 2 * 2 * DD, counts, N_NODES);
    wprep_kernel<<<dim3(8, 8), 128>>>(W1, W2, whi, wlo);
    count_kernel<<<(E_EDGES + 255) / 256, 256>>>(edst, counts);
    scan_pass1<<<SCAN_BLOCKS, 256>>>(counts, blocksums);
    scan_pass2<<<1, 1>>>(blocksums, rowptr);
    scan_pass3<<<SCAN_BLOCKS, 256>>>(counts, blocksums, rowptr, cursor);
    fill_kernel<<<(E_EDGES + 255) / 256, 256>>>(esrc, edst, cursor, srcsorted);

    for (int l = 0; l < NLAYERS; l++) {
        float* st1 = stats + (l * 2 + 0) * 2 * DD;
        float* st2 = stats + (l * 2 + 1) * 2 * DD;

        if (l == 0) {
            spmm_fused_kernel<false><<<SPMM_BLOCKS, 256>>>(
                x, nullptr, nullptr, nullptr, rowptr, srcsorted, eps, l, gid,
                pooled, gp + (size_t)l * GG * DD);
        } else {
            float* st2p = stats + ((l - 1) * 2 + 1) * 2 * DD;
            spmm_fused_kernel<true><<<SPMM_BLOCKS, 256>>>(
                z2, st2p, g2 + (l - 1) * DD, beta2 + (l - 1) * DD,
                rowptr, srcsorted, eps, l, gid,
                pooled, gp + (size_t)l * GG * DD);
        }
        mma_gemm_kernel<<<MTILES, 256, SM_TOTAL>>>(
            pooled, nullptr, nullptr, nullptr,
            whi + (size_t)l * DD * DD, wlo + (size_t)l * DD * DD,
            b1 + l * DD, z1, st1);
        mma_gemm_kernel<<<MTILES, 256, SM_TOTAL>>>(
            z1, st1, g1 + l * DD, beta1 + l * DD,
            whi + (size_t)(4 + l) * DD * DD, wlo + (size_t)(4 + l) * DD * DD,
            b2 + l * DD, z2, st2);
    }
    pool_final_kernel<<<(N_NODES + POOL_ROWS - 1) / POOL_ROWS, 128>>>(
        z2, stats + ((NLAYERS - 1) * 2 + 1) * 2 * DD,
        g2 + (NLAYERS - 1) * DD, beta2 + (NLAYERS - 1) * DD, gid,
        gp + (size_t)NLAYERS * GG * DD);
    readout_kernel<<<GG, 128>>>(gp, Wp, bp, out);
}